// round 5
// baseline (speedup 1.0000x reference)
#include <cuda_runtime.h>

// ---------------------------------------------------------------------------
// EqProp free-phase relaxation, T=30 steps.
// Key simplifications (states always in [0,1] => rho(s)=s, rhop(s)=1):
//   n0 = clip(0.8*s0 + 0.2*(s1@W0^T + b0))
//   n1 = clip(0.8*s1 + 0.2*(s2@W1^T + s0@W0 + b1))
//   n2 = clip(0.8*s2 + 0.2*(c2 + s1@W1)),  c2 = clip(data)@W2^T + b2  (precomputed)
// W0,W1 pre-transposed once so every GEMM is NT (K-contiguous both sides).
// ---------------------------------------------------------------------------

#define BM 128
#define BN 128
#define BK 16
#define TM 8
#define TN 8

#define BATCH 2048
#define NL0 1024
#define NL1 2048
#define NL2 2048

// Scratch (device globals: the sanctioned no-alloc workaround). ~120 MB.
__device__ float g_s0[2][(size_t)BATCH * NL0];
__device__ float g_s1[2][(size_t)BATCH * NL1];
__device__ float g_s2[2][(size_t)BATCH * NL2];
__device__ float g_c2[(size_t)BATCH * NL2];
__device__ float g_W0T[(size_t)NL1 * NL0];   // W0T[j][i] = W0[i][j]
__device__ float g_W1T[(size_t)NL2 * NL1];   // W1T[j][k] = W1[k][j]

// ---------------------------------------------------------------------------
__global__ void transpose_k(const float* __restrict__ in, float* __restrict__ out,
                            int R, int C) {
    __shared__ float tile[32][33];
    int c0 = blockIdx.x * 32, r0 = blockIdx.y * 32;
    int tx = threadIdx.x, ty = threadIdx.y;   // block (32, 8); R,C multiples of 32
#pragma unroll
    for (int i = 0; i < 32; i += 8)
        tile[ty + i][tx] = in[(size_t)(r0 + ty + i) * C + (c0 + tx)];
    __syncthreads();
#pragma unroll
    for (int i = 0; i < 32; i += 8)
        out[(size_t)(c0 + ty + i) * R + (r0 + tx)] = tile[tx][ty + i];
}

// ---------------------------------------------------------------------------
// Fused NT GEMM: C[M,N] = sum_k A0[m,k]*B0[n,k] (+ sum_k A1[m,k]*B1[n,k])
// epilogue: update ? clip(0.8*prev + 0.2*(acc + bias? + extra?)) : acc + bias
// All dims divisible by tile sizes -> no bounds checks.
// ---------------------------------------------------------------------------
__global__ __launch_bounds__(256)
void gemm_fused(const float* __restrict__ A0, const float* __restrict__ Bm0, int K0,
                const float* __restrict__ A1, const float* __restrict__ Bm1, int K1,
                const float* __restrict__ bias, const float* __restrict__ prev,
                const float* __restrict__ extra, float* __restrict__ C,
                int N, int clampA, int update) {
    __shared__ __align__(16) float As[2][BK][BM + 4];
    __shared__ __align__(16) float Bs[2][BK][BN + 4];

    const int tid = threadIdx.x;
    const int tx = tid & 15;          // output micro-col group
    const int ty = tid >> 4;          // output micro-row group
    const int mBase = blockIdx.y * BM;
    const int nBase = blockIdx.x * BN;
    const int nkb0 = K0 / BK;
    const int nkb = nkb0 + K1 / BK;

    float4 pa[2], pb[2];

    auto fetch = [&](int kb) {
        const float* Ap; const float* Bp; int ld, koff;
        if (kb < nkb0) { Ap = A0; Bp = Bm0; ld = K0; koff = kb * BK; }
        else           { Ap = A1; Bp = Bm1; ld = K1; koff = (kb - nkb0) * BK; }
#pragma unroll
        for (int it = 0; it < 2; ++it) {
            int q = tid + it * 256;
            int row = q >> 2, k4 = q & 3;
            pa[it] = *reinterpret_cast<const float4*>(
                Ap + (size_t)(mBase + row) * ld + koff + k4 * 4);
            pb[it] = *reinterpret_cast<const float4*>(
                Bp + (size_t)(nBase + row) * ld + koff + k4 * 4);
        }
        if (clampA) {
#pragma unroll
            for (int it = 0; it < 2; ++it) {
                pa[it].x = fminf(fmaxf(pa[it].x, 0.f), 1.f);
                pa[it].y = fminf(fmaxf(pa[it].y, 0.f), 1.f);
                pa[it].z = fminf(fmaxf(pa[it].z, 0.f), 1.f);
                pa[it].w = fminf(fmaxf(pa[it].w, 0.f), 1.f);
            }
        }
    };
    auto stash = [&](int buf) {
#pragma unroll
        for (int it = 0; it < 2; ++it) {
            int q = tid + it * 256;
            int row = q >> 2, k4 = q & 3;
            As[buf][k4 * 4 + 0][row] = pa[it].x;
            As[buf][k4 * 4 + 1][row] = pa[it].y;
            As[buf][k4 * 4 + 2][row] = pa[it].z;
            As[buf][k4 * 4 + 3][row] = pa[it].w;
            Bs[buf][k4 * 4 + 0][row] = pb[it].x;
            Bs[buf][k4 * 4 + 1][row] = pb[it].y;
            Bs[buf][k4 * 4 + 2][row] = pb[it].z;
            Bs[buf][k4 * 4 + 3][row] = pb[it].w;
        }
    };

    float acc[TM][TN];
#pragma unroll
    for (int i = 0; i < TM; ++i)
#pragma unroll
        for (int j = 0; j < TN; ++j) acc[i][j] = 0.f;

    fetch(0);
    stash(0);
    __syncthreads();

    int cur = 0;
    for (int kb = 0; kb < nkb; ++kb) {
        if (kb + 1 < nkb) fetch(kb + 1);
#pragma unroll
        for (int kk = 0; kk < BK; ++kk) {
            float4 a0 = *reinterpret_cast<const float4*>(&As[cur][kk][ty * TM]);
            float4 a1 = *reinterpret_cast<const float4*>(&As[cur][kk][ty * TM + 4]);
            float4 b0v = *reinterpret_cast<const float4*>(&Bs[cur][kk][tx * TN]);
            float4 b1v = *reinterpret_cast<const float4*>(&Bs[cur][kk][tx * TN + 4]);
            float a[TM] = {a0.x, a0.y, a0.z, a0.w, a1.x, a1.y, a1.z, a1.w};
            float b[TN] = {b0v.x, b0v.y, b0v.z, b0v.w, b1v.x, b1v.y, b1v.z, b1v.w};
#pragma unroll
            for (int i = 0; i < TM; ++i)
#pragma unroll
                for (int j = 0; j < TN; ++j)
                    acc[i][j] += a[i] * b[j];
        }
        if (kb + 1 < nkb) { stash(cur ^ 1); __syncthreads(); cur ^= 1; }
    }

    // Epilogue
#pragma unroll
    for (int i = 0; i < TM; ++i) {
        int r = mBase + ty * TM + i;
        size_t base = (size_t)r * N + nBase + tx * TN;
#pragma unroll
        for (int j = 0; j < TN; ++j) {
            float v = acc[i][j];
            if (bias) v += bias[nBase + tx * TN + j];
            if (update) {
                if (extra) v += extra[base + j];
                float p = prev[base + j];
                v = 0.8f * p + 0.2f * v;
                v = fminf(fmaxf(v, 0.f), 1.f);
            }
            C[base + j] = v;
        }
    }
}

// ---------------------------------------------------------------------------
__global__ void pack_out(float* __restrict__ out,
                         const float* __restrict__ a,
                         const float* __restrict__ b,
                         const float* __restrict__ c) {
    const size_t n0 = (size_t)BATCH * NL0;
    const size_t n1 = (size_t)BATCH * NL1;
    const size_t n2 = (size_t)BATCH * NL2;
    size_t stride = (size_t)gridDim.x * blockDim.x;
    for (size_t i = (size_t)blockIdx.x * blockDim.x + threadIdx.x;
         i < n0 + n1 + n2; i += stride) {
        float v;
        if (i < n0)            v = a[i];
        else if (i < n0 + n1)  v = b[i - n0];
        else                   v = c[i - n0 - n1];
        out[i] = v;
    }
}

// ---------------------------------------------------------------------------
extern "C" void kernel_launch(void* const* d_in, const int* in_sizes, int n_in,
                              void* d_out, int out_size) {
    (void)in_sizes; (void)n_in; (void)out_size;
    const float* s0   = (const float*)d_in[0];
    const float* s1   = (const float*)d_in[1];
    const float* s2   = (const float*)d_in[2];
    const float* data = (const float*)d_in[3];
    const float* W0   = (const float*)d_in[4];
    const float* b0   = (const float*)d_in[5];
    const float* W1   = (const float*)d_in[6];
    const float* b1   = (const float*)d_in[7];
    const float* W2   = (const float*)d_in[8];
    const float* b2   = (const float*)d_in[9];

    float *ps0, *ps1, *ps2, *pc2, *pW0T, *pW1T;
    cudaGetSymbolAddress((void**)&ps0,  g_s0);
    cudaGetSymbolAddress((void**)&ps1,  g_s1);
    cudaGetSymbolAddress((void**)&ps2,  g_s2);
    cudaGetSymbolAddress((void**)&pc2,  g_c2);
    cudaGetSymbolAddress((void**)&pW0T, g_W0T);
    cudaGetSymbolAddress((void**)&pW1T, g_W1T);

    const size_t n0 = (size_t)BATCH * NL0;
    const size_t n1 = (size_t)BATCH * NL1;
    const size_t n2 = (size_t)BATCH * NL2;

    // states -> ping buffer 0
    cudaMemcpyAsync(ps0, s0, n0 * sizeof(float), cudaMemcpyDeviceToDevice);
    cudaMemcpyAsync(ps1, s1, n1 * sizeof(float), cudaMemcpyDeviceToDevice);
    cudaMemcpyAsync(ps2, s2, n2 * sizeof(float), cudaMemcpyDeviceToDevice);

    // weight transposes (once per launch)
    dim3 tb(32, 8);
    transpose_k<<<dim3(NL1 / 32, NL0 / 32), tb>>>(W0, pW0T, NL0, NL1);
    transpose_k<<<dim3(NL2 / 32, NL1 / 32), tb>>>(W1, pW1T, NL1, NL2);

    // c2 = clip(data) @ W2^T + b2   (step-invariant input drive)
    gemm_fused<<<dim3(NL2 / BN, BATCH / BM), 256>>>(
        data, W2, NL2, nullptr, nullptr, 0,
        b2, nullptr, nullptr, pc2, NL2, /*clampA=*/1, /*update=*/0);

    for (int t = 0; t < 30; ++t) {
        int cur = t & 1, nxt = cur ^ 1;
        float* s0c = ps0 + (size_t)cur * n0; float* s0n = ps0 + (size_t)nxt * n0;
        float* s1c = ps1 + (size_t)cur * n1; float* s1n = ps1 + (size_t)nxt * n1;
        float* s2c = ps2 + (size_t)cur * n2; float* s2n = ps2 + (size_t)nxt * n2;

        // n0 = clip(0.8*s0 + 0.2*(s1 @ W0^T + b0))        [2048 x 1024], K=2048
        gemm_fused<<<dim3(NL0 / BN, BATCH / BM), 256>>>(
            s1c, W0, NL1, nullptr, nullptr, 0,
            b0, s0c, nullptr, s0n, NL0, 0, 1);

        // n1 = clip(0.8*s1 + 0.2*(s2 @ W1^T + s0 @ W0 + b1))  [2048 x 2048]
        gemm_fused<<<dim3(NL1 / BN, BATCH / BM), 256>>>(
            s2c, W1, NL2, s0c, pW0T, NL0,
            b1, s1c, nullptr, s1n, NL1, 0, 1);

        // n2 = clip(0.8*s2 + 0.2*(c2 + s1 @ W1))          [2048 x 2048], K=2048
        gemm_fused<<<dim3(NL2 / BN, BATCH / BM), 256>>>(
            s1c, pW1T, NL1, nullptr, nullptr, 0,
            nullptr, s2c, pc2, s2n, NL2, 0, 1);
    }

    // after 30 steps (even), final states sit in buffer 0
    pack_out<<<2048, 256>>>((float*)d_out, ps0, ps1, ps2);
}

// round 6
// speedup vs baseline: 1.0464x; 1.0464x over previous
#include <cuda_runtime.h>

// ---------------------------------------------------------------------------
// EqProp free-phase relaxation, T=30 steps.
// Key simplifications (states always in [0,1] => rho(s)=s, rhop(s)=1):
//   n0 = clip(0.8*s0 + 0.2*(s1@W0^T + b0))
//   n1 = clip(0.8*s1 + 0.2*(s2@W1^T + s0@W0 + b1))
//   n2 = clip(0.8*s2 + 0.2*(c2 + s1@W1)),  c2 = clip(data)@W2^T + b2  (precomputed)
// W0,W1 pre-transposed once so every GEMM is NT (K-contiguous both sides).
// ---------------------------------------------------------------------------

#define BM 128
#define BN 128
#define BK 16
#define TM 8
#define TN 8

#define BATCH 2048
#define NL0 1024
#define NL1 2048
#define NL2 2048

// Scratch (device globals: the sanctioned no-alloc workaround). ~120 MB.
__device__ float g_s0[2][(size_t)BATCH * NL0];
__device__ float g_s1[2][(size_t)BATCH * NL1];
__device__ float g_s2[2][(size_t)BATCH * NL2];
__device__ float g_c2[(size_t)BATCH * NL2];
__device__ float g_W0T[(size_t)NL1 * NL0];   // W0T[j][i] = W0[i][j]
__device__ float g_W1T[(size_t)NL2 * NL1];   // W1T[j][k] = W1[k][j]

// ---------------------------------------------------------------------------
__global__ void transpose_k(const float* __restrict__ in, float* __restrict__ out,
                            int R, int C) {
    __shared__ float tile[32][33];
    int c0 = blockIdx.x * 32, r0 = blockIdx.y * 32;
    int tx = threadIdx.x, ty = threadIdx.y;   // block (32, 8); R,C multiples of 32
#pragma unroll
    for (int i = 0; i < 32; i += 8)
        tile[ty + i][tx] = in[(size_t)(r0 + ty + i) * C + (c0 + tx)];
    __syncthreads();
#pragma unroll
    for (int i = 0; i < 32; i += 8)
        out[(size_t)(c0 + ty + i) * R + (r0 + tx)] = tile[tx][ty + i];
}

// ---------------------------------------------------------------------------
// Fused NT GEMM: C[M,N] = sum_k A0[m,k]*B0[n,k] (+ sum_k A1[m,k]*B1[n,k])
// epilogue: update ? clip(0.8*prev + 0.2*(acc + bias? + extra?)) : acc + bias
// All dims divisible by tile sizes -> no bounds checks.
// ---------------------------------------------------------------------------
__global__ __launch_bounds__(256)
void gemm_fused(const float* __restrict__ A0, const float* __restrict__ Bm0, int K0,
                const float* __restrict__ A1, const float* __restrict__ Bm1, int K1,
                const float* __restrict__ bias, const float* __restrict__ prev,
                const float* __restrict__ extra, float* __restrict__ C,
                int N, int clampA, int update) {
    __shared__ __align__(16) float As[2][BK][BM + 4];
    __shared__ __align__(16) float Bs[2][BK][BN + 4];

    const int tid = threadIdx.x;
    const int tx = tid & 15;          // output micro-col group
    const int ty = tid >> 4;          // output micro-row group
    const int mBase = blockIdx.y * BM;
    const int nBase = blockIdx.x * BN;
    const int nkb0 = K0 / BK;
    const int nkb = nkb0 + K1 / BK;

    float4 pa[2], pb[2];

    auto fetch = [&](int kb) {
        const float* Ap; const float* Bp; int ld, koff;
        if (kb < nkb0) { Ap = A0; Bp = Bm0; ld = K0; koff = kb * BK; }
        else           { Ap = A1; Bp = Bm1; ld = K1; koff = (kb - nkb0) * BK; }
#pragma unroll
        for (int it = 0; it < 2; ++it) {
            int q = tid + it * 256;
            int row = q >> 2, k4 = q & 3;
            pa[it] = *reinterpret_cast<const float4*>(
                Ap + (size_t)(mBase + row) * ld + koff + k4 * 4);
            pb[it] = *reinterpret_cast<const float4*>(
                Bp + (size_t)(nBase + row) * ld + koff + k4 * 4);
        }
        if (clampA) {
#pragma unroll
            for (int it = 0; it < 2; ++it) {
                pa[it].x = fminf(fmaxf(pa[it].x, 0.f), 1.f);
                pa[it].y = fminf(fmaxf(pa[it].y, 0.f), 1.f);
                pa[it].z = fminf(fmaxf(pa[it].z, 0.f), 1.f);
                pa[it].w = fminf(fmaxf(pa[it].w, 0.f), 1.f);
            }
        }
    };
    auto stash = [&](int buf) {
#pragma unroll
        for (int it = 0; it < 2; ++it) {
            int q = tid + it * 256;
            int row = q >> 2, k4 = q & 3;
            As[buf][k4 * 4 + 0][row] = pa[it].x;
            As[buf][k4 * 4 + 1][row] = pa[it].y;
            As[buf][k4 * 4 + 2][row] = pa[it].z;
            As[buf][k4 * 4 + 3][row] = pa[it].w;
            Bs[buf][k4 * 4 + 0][row] = pb[it].x;
            Bs[buf][k4 * 4 + 1][row] = pb[it].y;
            Bs[buf][k4 * 4 + 2][row] = pb[it].z;
            Bs[buf][k4 * 4 + 3][row] = pb[it].w;
        }
    };

    float acc[TM][TN];
#pragma unroll
    for (int i = 0; i < TM; ++i)
#pragma unroll
        for (int j = 0; j < TN; ++j) acc[i][j] = 0.f;

    fetch(0);
    stash(0);
    __syncthreads();

    int cur = 0;
    for (int kb = 0; kb < nkb; ++kb) {
        if (kb + 1 < nkb) fetch(kb + 1);
#pragma unroll
        for (int kk = 0; kk < BK; ++kk) {
            float4 a0 = *reinterpret_cast<const float4*>(&As[cur][kk][ty * TM]);
            float4 a1 = *reinterpret_cast<const float4*>(&As[cur][kk][ty * TM + 4]);
            float4 b0v = *reinterpret_cast<const float4*>(&Bs[cur][kk][tx * TN]);
            float4 b1v = *reinterpret_cast<const float4*>(&Bs[cur][kk][tx * TN + 4]);
            float a[TM] = {a0.x, a0.y, a0.z, a0.w, a1.x, a1.y, a1.z, a1.w};
            float b[TN] = {b0v.x, b0v.y, b0v.z, b0v.w, b1v.x, b1v.y, b1v.z, b1v.w};
#pragma unroll
            for (int i = 0; i < TM; ++i)
#pragma unroll
                for (int j = 0; j < TN; ++j)
                    acc[i][j] += a[i] * b[j];
        }
        if (kb + 1 < nkb) { stash(cur ^ 1); __syncthreads(); cur ^= 1; }
    }

    // Epilogue
#pragma unroll
    for (int i = 0; i < TM; ++i) {
        int r = mBase + ty * TM + i;
        size_t base = (size_t)r * N + nBase + tx * TN;
#pragma unroll
        for (int j = 0; j < TN; ++j) {
            float v = acc[i][j];
            if (bias) v += bias[nBase + tx * TN + j];
            if (update) {
                if (extra) v += extra[base + j];
                float p = prev[base + j];
                v = 0.8f * p + 0.2f * v;
                v = fminf(fmaxf(v, 0.f), 1.f);
            }
            C[base + j] = v;
        }
    }
}

// ---------------------------------------------------------------------------
__global__ void pack_out(float* __restrict__ out,
                         const float* __restrict__ a,
                         const float* __restrict__ b,
                         const float* __restrict__ c) {
    const size_t n0 = (size_t)BATCH * NL0;
    const size_t n1 = (size_t)BATCH * NL1;
    const size_t n2 = (size_t)BATCH * NL2;
    size_t stride = (size_t)gridDim.x * blockDim.x;
    for (size_t i = (size_t)blockIdx.x * blockDim.x + threadIdx.x;
         i < n0 + n1 + n2; i += stride) {
        float v;
        if (i < n0)            v = a[i];
        else if (i < n0 + n1)  v = b[i - n0];
        else                   v = c[i - n0 - n1];
        out[i] = v;
    }
}

// ---------------------------------------------------------------------------
extern "C" void kernel_launch(void* const* d_in, const int* in_sizes, int n_in,
                              void* d_out, int out_size) {
    (void)in_sizes; (void)n_in; (void)out_size;
    const float* s0   = (const float*)d_in[0];
    const float* s1   = (const float*)d_in[1];
    const float* s2   = (const float*)d_in[2];
    const float* data = (const float*)d_in[3];
    const float* W0   = (const float*)d_in[4];
    const float* b0   = (const float*)d_in[5];
    const float* W1   = (const float*)d_in[6];
    const float* b1   = (const float*)d_in[7];
    const float* W2   = (const float*)d_in[8];
    const float* b2   = (const float*)d_in[9];

    float *ps0, *ps1, *ps2, *pc2, *pW0T, *pW1T;
    cudaGetSymbolAddress((void**)&ps0,  g_s0);
    cudaGetSymbolAddress((void**)&ps1,  g_s1);
    cudaGetSymbolAddress((void**)&ps2,  g_s2);
    cudaGetSymbolAddress((void**)&pc2,  g_c2);
    cudaGetSymbolAddress((void**)&pW0T, g_W0T);
    cudaGetSymbolAddress((void**)&pW1T, g_W1T);

    const size_t n0 = (size_t)BATCH * NL0;
    const size_t n1 = (size_t)BATCH * NL1;
    const size_t n2 = (size_t)BATCH * NL2;

    // states -> ping buffer 0
    cudaMemcpyAsync(ps0, s0, n0 * sizeof(float), cudaMemcpyDeviceToDevice);
    cudaMemcpyAsync(ps1, s1, n1 * sizeof(float), cudaMemcpyDeviceToDevice);
    cudaMemcpyAsync(ps2, s2, n2 * sizeof(float), cudaMemcpyDeviceToDevice);

    // weight transposes (once per launch)
    dim3 tb(32, 8);
    transpose_k<<<dim3(NL1 / 32, NL0 / 32), tb>>>(W0, pW0T, NL0, NL1);
    transpose_k<<<dim3(NL2 / 32, NL1 / 32), tb>>>(W1, pW1T, NL1, NL2);

    // c2 = clip(data) @ W2^T + b2   (step-invariant input drive)
    gemm_fused<<<dim3(NL2 / BN, BATCH / BM), 256>>>(
        data, W2, NL2, nullptr, nullptr, 0,
        b2, nullptr, nullptr, pc2, NL2, /*clampA=*/1, /*update=*/0);

    for (int t = 0; t < 30; ++t) {
        int cur = t & 1, nxt = cur ^ 1;
        float* s0c = ps0 + (size_t)cur * n0; float* s0n = ps0 + (size_t)nxt * n0;
        float* s1c = ps1 + (size_t)cur * n1; float* s1n = ps1 + (size_t)nxt * n1;
        float* s2c = ps2 + (size_t)cur * n2; float* s2n = ps2 + (size_t)nxt * n2;

        // n0 = clip(0.8*s0 + 0.2*(s1 @ W0^T + b0))        [2048 x 1024], K=2048
        gemm_fused<<<dim3(NL0 / BN, BATCH / BM), 256>>>(
            s1c, W0, NL1, nullptr, nullptr, 0,
            b0, s0c, nullptr, s0n, NL0, 0, 1);

        // n1 = clip(0.8*s1 + 0.2*(s2 @ W1^T + s0 @ W0 + b1))  [2048 x 2048]
        gemm_fused<<<dim3(NL1 / BN, BATCH / BM), 256>>>(
            s2c, W1, NL2, s0c, pW0T, NL0,
            b1, s1c, nullptr, s1n, NL1, 0, 1);

        // n2 = clip(0.8*s2 + 0.2*(c2 + s1 @ W1))          [2048 x 2048], K=2048
        gemm_fused<<<dim3(NL2 / BN, BATCH / BM), 256>>>(
            s1c, pW1T, NL1, nullptr, nullptr, 0,
            nullptr, s2c, pc2, s2n, NL2, 0, 1);
    }

    // after 30 steps (even), final states sit in buffer 0
    pack_out<<<2048, 256>>>((float*)d_out, ps0, ps1, ps2);
}

// round 11
// speedup vs baseline: 4.9535x; 4.7341x over previous
#include <cuda_runtime.h>
#include <cuda_fp16.h>
#include <cstdint>

typedef unsigned int u32;
typedef unsigned long long u64;

#define BATCH 2048
#define NL0 1024
#define NL1 2048
#define NL2 2048

// tcgen05 is arch-specific: only emit it in arch/family-specific device passes.
#if defined(__CUDA_ARCH__) && (defined(__CUDA_ARCH_FEAT_SM103_ALL) || \
    defined(__CUDA_ARCH_FEAT_SM100_ALL) || \
    (defined(__CUDA_ARCH_SPECIFIC__) && (__CUDA_ARCH_SPECIFIC__ >= 1000)) || \
    (defined(__CUDA_ARCH_FAMILY_SPECIFIC__) && (__CUDA_ARCH_FAMILY_SPECIFIC__ >= 1000)))
#define EQ_TC 1
#else
#define EQ_TC 0
#endif

// ---- device scratch (no-alloc rule) ----
__device__ float  g_s0f[2][(size_t)BATCH * NL0];
__device__ float  g_s1f[2][(size_t)BATCH * NL1];
__device__ float  g_s2f[2][(size_t)BATCH * NL2];
__device__ __half g_s0h[2][(size_t)BATCH * NL0], g_s0l[2][(size_t)BATCH * NL0];
__device__ __half g_s1h[2][(size_t)BATCH * NL1], g_s1l[2][(size_t)BATCH * NL1];
__device__ __half g_s2h[2][(size_t)BATCH * NL2], g_s2l[2][(size_t)BATCH * NL2];
__device__ float  g_c2[(size_t)BATCH * NL2];
__device__ __half g_dh[(size_t)BATCH * NL2], g_dl[(size_t)BATCH * NL2];
__device__ __half g_W0h[(size_t)NL0 * NL1],  g_W0l[(size_t)NL0 * NL1];
__device__ __half g_W0Th[(size_t)NL1 * NL0], g_W0Tl[(size_t)NL1 * NL0];
__device__ __half g_W1h[(size_t)NL1 * NL2],  g_W1l[(size_t)NL1 * NL2];
__device__ __half g_W1Th[(size_t)NL2 * NL1], g_W1Tl[(size_t)NL2 * NL1];
__device__ __half g_W2h[(size_t)NL2 * NL2],  g_W2l[(size_t)NL2 * NL2];

#if EQ_TC
// ---- PTX helpers (tcgen05 path only) ----
__device__ __forceinline__ u32 smem_u32(const void* p) {
    u32 a;
    asm("{ .reg .u64 t; cvta.to.shared.u64 t, %1; cvt.u32.u64 %0, t; }" : "=r"(a) : "l"(p));
    return a;
}
__device__ __forceinline__ bool elect_one() {
    u32 p;
    asm volatile("{\n\t.reg .pred p;\n\telect.sync _|p, 0xFFFFFFFF;\n\tselp.b32 %0, 1, 0, p;\n\t}" : "=r"(p));
    return p != 0;
}
__device__ __forceinline__ void mbar_wait(u32 mbar, u32 parity) {
    u32 done;
    asm volatile("{\n\t.reg .pred p;\n\t"
                 "mbarrier.try_wait.parity.acquire.cta.shared::cta.b64 p, [%1], %2;\n\t"
                 "selp.b32 %0, 1, 0, p;\n\t}" : "=r"(done) : "r"(mbar), "r"(parity) : "memory");
    while (!done)
        asm volatile("{\n\t.reg .pred p;\n\t"
                     "mbarrier.try_wait.parity.acquire.cta.shared::cta.b64 p, [%1], %2, 0x989680;\n\t"
                     "selp.b32 %0, 1, 0, p;\n\t}" : "=r"(done) : "r"(mbar), "r"(parity) : "memory");
}
__device__ __forceinline__ void mma_f16_ss(u32 d, u64 a, u64 b, u32 idesc, u32 acc) {
    asm volatile("{\n\t.reg .pred p;\n\tsetp.ne.u32 p, %5, 0;\n\t"
                 "tcgen05.mma.cta_group::1.kind::f16 [%0], %1, %2, %3, {%4, %4, %4, %4}, p;\n\t}"
                 :: "r"(d), "l"(a), "l"(b), "r"(idesc), "r"(0u), "r"(acc) : "memory");
}
__device__ __forceinline__ u64 sdesc(u32 addr) {   // SW128, v1, SBO=64, LBO=1
    return (2ull << 61) | (1ull << 46) | (64ull << 32) | (1ull << 16) | ((u64)(addr >> 4) & 0x3FFF);
}
__device__ __forceinline__ void cpa16(u32 dst, const void* src) {
    asm volatile("cp.async.cg.shared.global [%0], [%1], 16;" :: "r"(dst), "l"(src) : "memory");
}
#define TC_LD32(r, addr) \
    asm volatile("tcgen05.ld.sync.aligned.32x32b.x32.b32 " \
        "{%0, %1, %2, %3, %4, %5, %6, %7, %8, %9, %10, %11, %12, %13, %14, %15, " \
        " %16, %17, %18, %19, %20, %21, %22, %23, %24, %25, %26, %27, %28, %29, %30, %31}, [%32];" \
        : "=r"((r)[0]),  "=r"((r)[1]),  "=r"((r)[2]),  "=r"((r)[3]), \
          "=r"((r)[4]),  "=r"((r)[5]),  "=r"((r)[6]),  "=r"((r)[7]), \
          "=r"((r)[8]),  "=r"((r)[9]),  "=r"((r)[10]), "=r"((r)[11]), \
          "=r"((r)[12]), "=r"((r)[13]), "=r"((r)[14]), "=r"((r)[15]), \
          "=r"((r)[16]), "=r"((r)[17]), "=r"((r)[18]), "=r"((r)[19]), \
          "=r"((r)[20]), "=r"((r)[21]), "=r"((r)[22]), "=r"((r)[23]), \
          "=r"((r)[24]), "=r"((r)[25]), "=r"((r)[26]), "=r"((r)[27]), \
          "=r"((r)[28]), "=r"((r)[29]), "=r"((r)[30]), "=r"((r)[31]) \
        : "r"(addr))
#endif  // EQ_TC

// ---- prep kernels ----
__global__ void decompose_k(const float* __restrict__ in, __half* __restrict__ hi,
                            __half* __restrict__ lo, size_t n4, int clampv) {
    size_t i = (size_t)blockIdx.x * blockDim.x + threadIdx.x;
    if (i >= n4) return;
    float4 x = reinterpret_cast<const float4*>(in)[i];
    if (clampv) {
        x.x = fminf(fmaxf(x.x, 0.f), 1.f); x.y = fminf(fmaxf(x.y, 0.f), 1.f);
        x.z = fminf(fmaxf(x.z, 0.f), 1.f); x.w = fminf(fmaxf(x.w, 0.f), 1.f);
    }
    __half h0 = __float2half_rn(x.x), h1 = __float2half_rn(x.y);
    __half h2 = __float2half_rn(x.z), h3 = __float2half_rn(x.w);
    reinterpret_cast<__half2*>(hi)[2*i+0] = __halves2half2(h0, h1);
    reinterpret_cast<__half2*>(hi)[2*i+1] = __halves2half2(h2, h3);
    reinterpret_cast<__half2*>(lo)[2*i+0] = __halves2half2(
        __float2half_rn(x.x - __half2float(h0)), __float2half_rn(x.y - __half2float(h1)));
    reinterpret_cast<__half2*>(lo)[2*i+1] = __halves2half2(
        __float2half_rn(x.z - __half2float(h2)), __float2half_rn(x.w - __half2float(h3)));
}

__global__ void transpose_decompose_k(const float* __restrict__ in,
                                      __half* __restrict__ oh, __half* __restrict__ ol,
                                      int R, int C) {
    __shared__ float t[32][33];
    int c0 = blockIdx.x * 32, r0 = blockIdx.y * 32;
    int tx = threadIdx.x, ty = threadIdx.y;   // (32,8)
#pragma unroll
    for (int i = 0; i < 32; i += 8)
        t[ty + i][tx] = in[(size_t)(r0 + ty + i) * C + (c0 + tx)];
    __syncthreads();
#pragma unroll
    for (int i = 0; i < 32; i += 8) {
        float x = t[tx][ty + i];
        __half h = __float2half_rn(x);
        size_t o = (size_t)(c0 + ty + i) * R + (r0 + tx);
        oh[o] = h; ol[o] = __float2half_rn(x - __half2float(h));
    }
}

__global__ void pack_out(float* __restrict__ out, const float* __restrict__ a,
                         const float* __restrict__ b, const float* __restrict__ c) {
    const size_t n0 = (size_t)BATCH * NL0, n1 = (size_t)BATCH * NL1, n2 = (size_t)BATCH * NL2;
    size_t stride = (size_t)gridDim.x * blockDim.x;
    for (size_t i = (size_t)blockIdx.x * blockDim.x + threadIdx.x; i < n0 + n1 + n2; i += stride)
        out[i] = (i < n0) ? a[i] : (i < n0 + n1) ? b[i - n0] : c[i - n0 - n1];
}

// ---------------------------------------------------------------------------
// Fused GEMM, 128x128 tile (fp16 split-2 operands, fp32 accumulate):
//   D[128,128] = A0(hi,lo) x B0(hi,lo)^T over K0  [+ A1(hi,lo) x B1(hi,lo)^T over K1]
//   epilogue: prev? clip(0.8*prev + 0.2*(D+bias?+extra?)) : D+bias
//   writes Cf fp32 and optionally Ch/Cl fp16 split.
// TC path: SS cg1 tcgen05 kind::f16, K chunk 64 (SW128), 3 split products,
//   warp 0 owns alloc(512)+MMA+commit (example-proven roles), double-buffered
//   cp.async stages with per-buffer commit/wait.
// ---------------------------------------------------------------------------
__global__ void __launch_bounds__(256, 1) gemm_tc(
    const __half* __restrict__ Ah0, const __half* __restrict__ Al0,
    const __half* __restrict__ Bh0, const __half* __restrict__ Bl0, int K0,
    const __half* __restrict__ Ah1, const __half* __restrict__ Al1,
    const __half* __restrict__ Bh1, const __half* __restrict__ Bl1, int K1,
    const float* __restrict__ bias, const float* __restrict__ prev,
    const float* __restrict__ extra,
    float* __restrict__ Cf, __half* __restrict__ Ch, __half* __restrict__ Cl, int N)
{
    extern __shared__ char smem_raw[];
#if EQ_TC
    constexpr int STAGE = 65536;                 // Ah,Al,Bh,Bl: 4 x 16KB
    const int tid = threadIdx.x, wid = tid >> 5, lid = tid & 31;
    u32 sb = (smem_u32(smem_raw) + 1023) & ~1023u;

    if (wid == 0) {
        asm volatile("tcgen05.alloc.cta_group::1.sync.aligned.shared::cta.b32 [%0], 512;"
                     :: "r"(sb) : "memory");
    }
    if (tid == 0) {
        asm volatile("mbarrier.init.shared.b64 [%0], 1;" :: "r"(sb + 16) : "memory");
        asm volatile("mbarrier.init.shared.b64 [%0], 1;" :: "r"(sb + 24) : "memory");
    }
    __syncthreads();
    u32 tmem;
    asm volatile("ld.shared.b32 %0, [%1];" : "=r"(tmem) : "r"(sb));

    const int mBase = blockIdx.y * 128, nBase = blockIdx.x * 128;
    const int nkb0 = K0 >> 6, nkb = nkb0 + (K1 >> 6);
    // idesc (kind::f16, fp16 A/B, fp32 acc): dtype=F32(bit4), N/8<<17, M/16<<24
    const u32 idesc = 0x10u | (16u << 17) | (8u << 24);

    for (int kb = 0; kb < nkb; ++kb) {
        const int buf = kb & 1;
        if (kb >= 2) mbar_wait(sb + 16 + 8 * buf, ((kb >> 1) - 1) & 1);

        const __half *Ah, *Al, *Bh, *Bl; int ldk, koff;
        if (kb < nkb0) { Ah = Ah0; Al = Al0; Bh = Bh0; Bl = Bl0; ldk = K0; koff = kb << 6; }
        else           { Ah = Ah1; Al = Al1; Bh = Bh1; Bl = Bl1; ldk = K1; koff = (kb - nkb0) << 6; }
        const u32 stg = sb + 1024 + buf * STAGE;

#pragma unroll
        for (int it = 0; it < 16; ++it) {        // 4096 16B units / 256 threads
            int u = tid + it * 256;
            const __half* src; u32 dbase; int v;
            if (u < 1024)      { v = u;        src = Ah + (size_t)(mBase + (v >> 3)) * ldk; dbase = stg; }
            else if (u < 2048) { v = u - 1024; src = Al + (size_t)(mBase + (v >> 3)) * ldk; dbase = stg + 16384; }
            else if (u < 3072) { v = u - 2048; src = Bh + (size_t)(nBase + (v >> 3)) * ldk; dbase = stg + 32768; }
            else               { v = u - 3072; src = Bl + (size_t)(nBase + (v >> 3)) * ldk; dbase = stg + 49152; }
            int row = v >> 3, slot = v & 7;
            cpa16(dbase + row * 128 + ((slot * 16) ^ ((row & 7) << 4)), src + koff + slot * 8);
        }
        asm volatile("cp.async.commit_group;" ::: "memory");
        asm volatile("cp.async.wait_group 0;" ::: "memory");
        asm volatile("fence.proxy.async.shared::cta;" ::: "memory");   // every writer thread
        __syncthreads();

        if (wid == 0 && elect_one()) {
            u64 dAh = sdesc(stg), dAl = sdesc(stg + 16384);
            u64 dBh = sdesc(stg + 32768), dBl = sdesc(stg + 49152);
#pragma unroll
            for (int ks = 0; ks < 4; ++ks) {     // 4 x K16 per chunk, 3 split products
                mma_f16_ss(tmem, dAh + ks * 2, dBh + ks * 2, idesc, (kb > 0) || (ks > 0));
                mma_f16_ss(tmem, dAh + ks * 2, dBl + ks * 2, idesc, 1);
                mma_f16_ss(tmem, dAl + ks * 2, dBh + ks * 2, idesc, 1);
            }
            asm volatile("tcgen05.commit.cta_group::1.mbarrier::arrive::one.shared::cluster.b64 [%0];"
                         :: "r"(sb + 16 + 8 * buf) : "memory");
        }
    }
    mbar_wait(sb + 16 + 8 * ((nkb - 1) & 1), ((nkb - 1) >> 1) & 1);
    asm volatile("tcgen05.fence::after_thread_sync;" ::: "memory");

    // Epilogue: 8 warps. warps 0-3: cols 0-63; warps 4-7: cols 64-127.
    const int row = mBase + (wid & 3) * 32 + lid;
    const int ch0 = (wid >> 2) * 64;
#pragma unroll
    for (int g = 0; g < 2; ++g) {
        const int c0 = ch0 + g * 32;
        u32 r_[32];
        TC_LD32(r_, tmem + c0);
        asm volatile("tcgen05.wait::ld.sync.aligned;" ::: "memory");
        float v[32];
#pragma unroll
        for (int j = 0; j < 32; ++j) v[j] = __uint_as_float(r_[j]);
        const size_t base = (size_t)row * N + nBase + c0;
        if (bias)
#pragma unroll
            for (int j = 0; j < 32; ++j) v[j] += __ldg(bias + nBase + c0 + j);
        if (prev) {
#pragma unroll
            for (int q = 0; q < 8; ++q) {
                float4 p = *reinterpret_cast<const float4*>(prev + base + q * 4);
                float4 e = make_float4(0.f, 0.f, 0.f, 0.f);
                if (extra) e = *reinterpret_cast<const float4*>(extra + base + q * 4);
                v[4*q+0] = fminf(fmaxf(0.8f * p.x + 0.2f * (v[4*q+0] + e.x), 0.f), 1.f);
                v[4*q+1] = fminf(fmaxf(0.8f * p.y + 0.2f * (v[4*q+1] + e.y), 0.f), 1.f);
                v[4*q+2] = fminf(fmaxf(0.8f * p.z + 0.2f * (v[4*q+2] + e.z), 0.f), 1.f);
                v[4*q+3] = fminf(fmaxf(0.8f * p.w + 0.2f * (v[4*q+3] + e.w), 0.f), 1.f);
            }
        }
#pragma unroll
        for (int q = 0; q < 8; ++q)
            *reinterpret_cast<float4*>(Cf + base + q * 4) =
                make_float4(v[4*q+0], v[4*q+1], v[4*q+2], v[4*q+3]);
        if (Ch)
#pragma unroll
            for (int j = 0; j < 32; j += 2) {
                __half h0 = __float2half_rn(v[j]), h1 = __float2half_rn(v[j+1]);
                *reinterpret_cast<__half2*>(Ch + base + j) = __halves2half2(h0, h1);
                *reinterpret_cast<__half2*>(Cl + base + j) = __halves2half2(
                    __float2half_rn(v[j] - __half2float(h0)),
                    __float2half_rn(v[j+1] - __half2float(h1)));
            }
    }
    asm volatile("tcgen05.fence::before_thread_sync;" ::: "memory");
    __syncthreads();
    if (tid == 0) {
        asm volatile("mbarrier.inval.shared.b64 [%0];" :: "r"(sb + 16) : "memory");
        asm volatile("mbarrier.inval.shared.b64 [%0];" :: "r"(sb + 24) : "memory");
    }
    __syncthreads();
    if (wid == 0)
        asm volatile("tcgen05.dealloc.cta_group::1.sync.aligned.b32 %0, 512;" :: "r"(tmem));
#else
    // ---------------- SIMT fp32 fallback (non-arch-specific pass) -----------
    float* As = reinterpret_cast<float*>(smem_raw);        // [16][132]
    float* Bs = As + 16 * 132;                             // [16][132]
    const int tid = threadIdx.x;
    const int tx = tid & 15, ty = tid >> 4;
    const int mBase = blockIdx.y * 128, nBase = blockIdx.x * 128;
    const int nkb0 = K0 >> 4, nkb = nkb0 + (K1 >> 4);
    const int lrow = tid >> 1, seg8 = tid & 1;
    float acc[8][8];
#pragma unroll
    for (int i = 0; i < 8; ++i)
#pragma unroll
        for (int j = 0; j < 8; ++j) acc[i][j] = 0.f;

    for (int kb = 0; kb < nkb; ++kb) {
        const __half *Ah, *Al, *Bh, *Bl; int ldk, koff;
        if (kb < nkb0) { Ah = Ah0; Al = Al0; Bh = Bh0; Bl = Bl0; ldk = K0; koff = kb << 4; }
        else           { Ah = Ah1; Al = Al1; Bh = Bh1; Bl = Bl1; ldk = K1; koff = (kb - nkb0) << 4; }
        {
            size_t off = (size_t)(mBase + lrow) * ldk + koff + seg8 * 8;
            uint4 hv = *reinterpret_cast<const uint4*>(Ah + off);
            uint4 lv = *reinterpret_cast<const uint4*>(Al + off);
            const __half2* hh = reinterpret_cast<const __half2*>(&hv);
            const __half2* ll = reinterpret_cast<const __half2*>(&lv);
#pragma unroll
            for (int p = 0; p < 4; ++p) {
                float2 hf = __half22float2(hh[p]);
                float2 lf = __half22float2(ll[p]);
                As[(seg8 * 8 + 2 * p + 0) * 132 + lrow] = hf.x + lf.x;
                As[(seg8 * 8 + 2 * p + 1) * 132 + lrow] = hf.y + lf.y;
            }
            off = (size_t)(nBase + lrow) * ldk + koff + seg8 * 8;
            hv = *reinterpret_cast<const uint4*>(Bh + off);
            lv = *reinterpret_cast<const uint4*>(Bl + off);
#pragma unroll
            for (int p = 0; p < 4; ++p) {
                float2 hf = __half22float2(hh[p]);
                float2 lf = __half22float2(ll[p]);
                Bs[(seg8 * 8 + 2 * p + 0) * 132 + lrow] = hf.x + lf.x;
                Bs[(seg8 * 8 + 2 * p + 1) * 132 + lrow] = hf.y + lf.y;
            }
        }
        __syncthreads();
#pragma unroll
        for (int kk = 0; kk < 16; ++kk) {
            float a[8], b[8];
#pragma unroll
            for (int i = 0; i < 8; ++i) a[i] = As[kk * 132 + ty * 8 + i];
#pragma unroll
            for (int j = 0; j < 8; ++j) b[j] = Bs[kk * 132 + tx * 8 + j];
#pragma unroll
            for (int i = 0; i < 8; ++i)
#pragma unroll
                for (int j = 0; j < 8; ++j) acc[i][j] += a[i] * b[j];
        }
        __syncthreads();
    }
#pragma unroll
    for (int i = 0; i < 8; ++i) {
        int r = mBase + ty * 8 + i;
        size_t base = (size_t)r * N + nBase + tx * 8;
        float v[8];
#pragma unroll
        for (int j = 0; j < 8; ++j) {
            v[j] = acc[i][j];
            if (bias) v[j] += bias[nBase + tx * 8 + j];
            if (prev) {
                float e = extra ? extra[base + j] : 0.f;
                v[j] = fminf(fmaxf(0.8f * prev[base + j] + 0.2f * (v[j] + e), 0.f), 1.f);
            }
            Cf[base + j] = v[j];
        }
        if (Ch)
#pragma unroll
            for (int j = 0; j < 8; j += 2) {
                __half h0 = __float2half_rn(v[j]), h1 = __float2half_rn(v[j+1]);
                *reinterpret_cast<__half2*>(Ch + base + j) = __halves2half2(h0, h1);
                *reinterpret_cast<__half2*>(Cl + base + j) = __halves2half2(
                    __float2half_rn(v[j]   - __half2float(h0)),
                    __float2half_rn(v[j+1] - __half2float(h1)));
            }
    }
#endif
}

// ---------------------------------------------------------------------------
extern "C" void kernel_launch(void* const* d_in, const int* in_sizes, int n_in,
                              void* d_out, int out_size) {
    (void)in_sizes; (void)n_in; (void)out_size;
    const float* s0   = (const float*)d_in[0];
    const float* s1   = (const float*)d_in[1];
    const float* s2   = (const float*)d_in[2];
    const float* data = (const float*)d_in[3];
    const float* W0   = (const float*)d_in[4];
    const float* b0   = (const float*)d_in[5];
    const float* W1   = (const float*)d_in[6];
    const float* b1   = (const float*)d_in[7];
    const float* W2   = (const float*)d_in[8];
    const float* b2   = (const float*)d_in[9];

    float *s0f, *s1f, *s2f, *c2;
    __half *s0h, *s0l, *s1h, *s1l, *s2h, *s2l, *dh, *dl;
    __half *W0h, *W0l, *W0Th, *W0Tl, *W1h, *W1l, *W1Th, *W1Tl, *W2h, *W2l;
    cudaGetSymbolAddress((void**)&s0f, g_s0f);   cudaGetSymbolAddress((void**)&s1f, g_s1f);
    cudaGetSymbolAddress((void**)&s2f, g_s2f);   cudaGetSymbolAddress((void**)&c2,  g_c2);
    cudaGetSymbolAddress((void**)&s0h, g_s0h);   cudaGetSymbolAddress((void**)&s0l, g_s0l);
    cudaGetSymbolAddress((void**)&s1h, g_s1h);   cudaGetSymbolAddress((void**)&s1l, g_s1l);
    cudaGetSymbolAddress((void**)&s2h, g_s2h);   cudaGetSymbolAddress((void**)&s2l, g_s2l);
    cudaGetSymbolAddress((void**)&dh,  g_dh);    cudaGetSymbolAddress((void**)&dl,  g_dl);
    cudaGetSymbolAddress((void**)&W0h, g_W0h);   cudaGetSymbolAddress((void**)&W0l, g_W0l);
    cudaGetSymbolAddress((void**)&W0Th, g_W0Th); cudaGetSymbolAddress((void**)&W0Tl, g_W0Tl);
    cudaGetSymbolAddress((void**)&W1h, g_W1h);   cudaGetSymbolAddress((void**)&W1l, g_W1l);
    cudaGetSymbolAddress((void**)&W1Th, g_W1Th); cudaGetSymbolAddress((void**)&W1Tl, g_W1Tl);
    cudaGetSymbolAddress((void**)&W2h, g_W2h);   cudaGetSymbolAddress((void**)&W2l, g_W2l);

    const size_t n0 = (size_t)BATCH * NL0, n1 = (size_t)BATCH * NL1, n2 = (size_t)BATCH * NL2;

    constexpr int SM = 2048 + 2 * 65536;   // align pad + 2 stages = 133,120 B
    cudaFuncSetAttribute(gemm_tc, cudaFuncAttributeMaxDynamicSharedMemorySize, SM);

    // prep: fp32 state copies + fp16 splits + weight splits/transposes
    cudaMemcpyAsync(s0f, s0, n0 * 4, cudaMemcpyDeviceToDevice);
    cudaMemcpyAsync(s1f, s1, n1 * 4, cudaMemcpyDeviceToDevice);
    cudaMemcpyAsync(s2f, s2, n2 * 4, cudaMemcpyDeviceToDevice);
    decompose_k<<<(int)(n0 / 4 / 256), 256>>>(s0, s0h, s0l, n0 / 4, 0);
    decompose_k<<<(int)(n1 / 4 / 256), 256>>>(s1, s1h, s1l, n1 / 4, 0);
    decompose_k<<<(int)(n2 / 4 / 256), 256>>>(s2, s2h, s2l, n2 / 4, 0);
    decompose_k<<<(int)(n2 / 4 / 256), 256>>>(data, dh, dl, n2 / 4, 1);
    decompose_k<<<(NL0 * NL1 / 4) / 256, 256>>>(W0, W0h, W0l, NL0 * NL1 / 4, 0);
    decompose_k<<<(NL1 * NL2 / 4) / 256, 256>>>(W1, W1h, W1l, NL1 * NL2 / 4, 0);
    decompose_k<<<(NL2 * NL2 / 4) / 256, 256>>>(W2, W2h, W2l, NL2 * NL2 / 4, 0);
    dim3 tb(32, 8);
    transpose_decompose_k<<<dim3(NL1 / 32, NL0 / 32), tb>>>(W0, W0Th, W0Tl, NL0, NL1);
    transpose_decompose_k<<<dim3(NL2 / 32, NL1 / 32), tb>>>(W1, W1Th, W1Tl, NL1, NL2);

    // c2 = clip(data) @ W2^T + b2  (step-invariant)
    gemm_tc<<<dim3(NL2 / 128, BATCH / 128), 256, SM>>>(
        dh, dl, W2h, W2l, NL2, nullptr, nullptr, nullptr, nullptr, 0,
        b2, nullptr, nullptr, c2, nullptr, nullptr, NL2);

    for (int t = 0; t < 30; ++t) {
        const size_t cu = (size_t)(t & 1), nx = cu ^ 1;
        // n0 = clip(0.8*s0 + 0.2*(s1 @ W0^T + b0))   K=2048, N=1024
        gemm_tc<<<dim3(NL0 / 128, BATCH / 128), 256, SM>>>(
            s1h + cu * n1, s1l + cu * n1, W0h, W0l, NL1,
            nullptr, nullptr, nullptr, nullptr, 0,
            b0, s0f + cu * n0, nullptr,
            s0f + nx * n0, s0h + nx * n0, s0l + nx * n0, NL0);
        // n1 = clip(0.8*s1 + 0.2*(s2 @ W1^T + s0 @ W0 + b1))   N=2048
        gemm_tc<<<dim3(NL1 / 128, BATCH / 128), 256, SM>>>(
            s2h + cu * n2, s2l + cu * n2, W1h, W1l, NL2,
            s0h + cu * n0, s0l + cu * n0, W0Th, W0Tl, NL0,
            b1, s1f + cu * n1, nullptr,
            s1f + nx * n1, s1h + nx * n1, s1l + nx * n1, NL1);
        // n2 = clip(0.8*s2 + 0.2*(c2 + s1 @ W1))   N=2048
        gemm_tc<<<dim3(NL2 / 128, BATCH / 128), 256, SM>>>(
            s1h + cu * n1, s1l + cu * n1, W1Th, W1Tl, NL1,
            nullptr, nullptr, nullptr, nullptr, 0,
            nullptr, s2f + cu * n2, c2,
            s2f + nx * n2, s2h + nx * n2, s2l + nx * n2, NL2);
    }

    pack_out<<<2048, 256>>>((float*)d_out, s0f, s1f, s2f);   // final in buffer 0
}

// round 12
// speedup vs baseline: 6.7412x; 1.3609x over previous
#include <cuda_runtime.h>
#include <cuda_fp16.h>
#include <cstdint>

typedef unsigned int u32;
typedef unsigned long long u64;

#define BATCH 2048
#define NL0 1024
#define NL1 2048
#define NL2 2048

// tcgen05 is arch-specific: only emit it in arch/family-specific device passes.
#if defined(__CUDA_ARCH__) && (defined(__CUDA_ARCH_FEAT_SM103_ALL) || \
    defined(__CUDA_ARCH_FEAT_SM100_ALL) || \
    (defined(__CUDA_ARCH_SPECIFIC__) && (__CUDA_ARCH_SPECIFIC__ >= 1000)) || \
    (defined(__CUDA_ARCH_FAMILY_SPECIFIC__) && (__CUDA_ARCH_FAMILY_SPECIFIC__ >= 1000)))
#define EQ_TC 1
#else
#define EQ_TC 0
#endif

// ---- device scratch (no-alloc rule) ----
__device__ float  g_s0f[2][(size_t)BATCH * NL0];
__device__ float  g_s1f[2][(size_t)BATCH * NL1];
__device__ float  g_s2f[2][(size_t)BATCH * NL2];
__device__ __half g_s0h[2][(size_t)BATCH * NL0], g_s0l[2][(size_t)BATCH * NL0];
__device__ __half g_s1h[2][(size_t)BATCH * NL1], g_s1l[2][(size_t)BATCH * NL1];
__device__ __half g_s2h[2][(size_t)BATCH * NL2], g_s2l[2][(size_t)BATCH * NL2];
__device__ float  g_c2[(size_t)BATCH * NL2];
__device__ __half g_dh[(size_t)BATCH * NL2], g_dl[(size_t)BATCH * NL2];
__device__ __half g_W0h[(size_t)NL0 * NL1],  g_W0l[(size_t)NL0 * NL1];
__device__ __half g_W0Th[(size_t)NL1 * NL0], g_W0Tl[(size_t)NL1 * NL0];
__device__ __half g_W1h[(size_t)NL1 * NL2],  g_W1l[(size_t)NL1 * NL2];
__device__ __half g_W1Th[(size_t)NL2 * NL1], g_W1Tl[(size_t)NL2 * NL1];
__device__ __half g_W2h[(size_t)NL2 * NL2],  g_W2l[(size_t)NL2 * NL2];

#if EQ_TC
// ---- PTX helpers (tcgen05 path only) ----
__device__ __forceinline__ u32 smem_u32(const void* p) {
    u32 a;
    asm("{ .reg .u64 t; cvta.to.shared.u64 t, %1; cvt.u32.u64 %0, t; }" : "=r"(a) : "l"(p));
    return a;
}
__device__ __forceinline__ bool elect_one() {
    u32 p;
    asm volatile("{\n\t.reg .pred p;\n\telect.sync _|p, 0xFFFFFFFF;\n\tselp.b32 %0, 1, 0, p;\n\t}" : "=r"(p));
    return p != 0;
}
__device__ __forceinline__ void mbar_wait(u32 mbar, u32 parity) {
    u32 done;
    asm volatile("{\n\t.reg .pred p;\n\t"
                 "mbarrier.try_wait.parity.acquire.cta.shared::cta.b64 p, [%1], %2;\n\t"
                 "selp.b32 %0, 1, 0, p;\n\t}" : "=r"(done) : "r"(mbar), "r"(parity) : "memory");
    while (!done)
        asm volatile("{\n\t.reg .pred p;\n\t"
                     "mbarrier.try_wait.parity.acquire.cta.shared::cta.b64 p, [%1], %2, 0x989680;\n\t"
                     "selp.b32 %0, 1, 0, p;\n\t}" : "=r"(done) : "r"(mbar), "r"(parity) : "memory");
}
__device__ __forceinline__ void mma_f16_ss(u32 d, u64 a, u64 b, u32 idesc, u32 acc) {
    asm volatile("{\n\t.reg .pred p;\n\tsetp.ne.u32 p, %5, 0;\n\t"
                 "tcgen05.mma.cta_group::1.kind::f16 [%0], %1, %2, %3, {%4, %4, %4, %4}, p;\n\t}"
                 :: "r"(d), "l"(a), "l"(b), "r"(idesc), "r"(0u), "r"(acc) : "memory");
}
__device__ __forceinline__ u64 sdesc(u32 addr) {   // SW128, v1, SBO=64, LBO=1
    return (2ull << 61) | (1ull << 46) | (64ull << 32) | (1ull << 16) | ((u64)(addr >> 4) & 0x3FFF);
}
__device__ __forceinline__ void cpa16(u32 dst, const void* src) {
    asm volatile("cp.async.cg.shared.global [%0], [%1], 16;" :: "r"(dst), "l"(src) : "memory");
}
#define TC_LD32(r, addr) \
    asm volatile("tcgen05.ld.sync.aligned.32x32b.x32.b32 " \
        "{%0, %1, %2, %3, %4, %5, %6, %7, %8, %9, %10, %11, %12, %13, %14, %15, " \
        " %16, %17, %18, %19, %20, %21, %22, %23, %24, %25, %26, %27, %28, %29, %30, %31}, [%32];" \
        : "=r"((r)[0]),  "=r"((r)[1]),  "=r"((r)[2]),  "=r"((r)[3]), \
          "=r"((r)[4]),  "=r"((r)[5]),  "=r"((r)[6]),  "=r"((r)[7]), \
          "=r"((r)[8]),  "=r"((r)[9]),  "=r"((r)[10]), "=r"((r)[11]), \
          "=r"((r)[12]), "=r"((r)[13]), "=r"((r)[14]), "=r"((r)[15]), \
          "=r"((r)[16]), "=r"((r)[17]), "=r"((r)[18]), "=r"((r)[19]), \
          "=r"((r)[20]), "=r"((r)[21]), "=r"((r)[22]), "=r"((r)[23]), \
          "=r"((r)[24]), "=r"((r)[25]), "=r"((r)[26]), "=r"((r)[27]), \
          "=r"((r)[28]), "=r"((r)[29]), "=r"((r)[30]), "=r"((r)[31]) \
        : "r"(addr))
#endif  // EQ_TC

// ---- prep kernels ----
__global__ void decompose_k(const float* __restrict__ in, __half* __restrict__ hi,
                            __half* __restrict__ lo, size_t n4, int clampv) {
    size_t i = (size_t)blockIdx.x * blockDim.x + threadIdx.x;
    if (i >= n4) return;
    float4 x = reinterpret_cast<const float4*>(in)[i];
    if (clampv) {
        x.x = fminf(fmaxf(x.x, 0.f), 1.f); x.y = fminf(fmaxf(x.y, 0.f), 1.f);
        x.z = fminf(fmaxf(x.z, 0.f), 1.f); x.w = fminf(fmaxf(x.w, 0.f), 1.f);
    }
    __half h0 = __float2half_rn(x.x), h1 = __float2half_rn(x.y);
    __half h2 = __float2half_rn(x.z), h3 = __float2half_rn(x.w);
    reinterpret_cast<__half2*>(hi)[2*i+0] = __halves2half2(h0, h1);
    reinterpret_cast<__half2*>(hi)[2*i+1] = __halves2half2(h2, h3);
    reinterpret_cast<__half2*>(lo)[2*i+0] = __halves2half2(
        __float2half_rn(x.x - __half2float(h0)), __float2half_rn(x.y - __half2float(h1)));
    reinterpret_cast<__half2*>(lo)[2*i+1] = __halves2half2(
        __float2half_rn(x.z - __half2float(h2)), __float2half_rn(x.w - __half2float(h3)));
}

__global__ void transpose_decompose_k(const float* __restrict__ in,
                                      __half* __restrict__ oh, __half* __restrict__ ol,
                                      int R, int C) {
    __shared__ float t[32][33];
    int c0 = blockIdx.x * 32, r0 = blockIdx.y * 32;
    int tx = threadIdx.x, ty = threadIdx.y;   // (32,8)
#pragma unroll
    for (int i = 0; i < 32; i += 8)
        t[ty + i][tx] = in[(size_t)(r0 + ty + i) * C + (c0 + tx)];
    __syncthreads();
#pragma unroll
    for (int i = 0; i < 32; i += 8) {
        float x = t[tx][ty + i];
        __half h = __float2half_rn(x);
        size_t o = (size_t)(c0 + ty + i) * R + (r0 + tx);
        oh[o] = h; ol[o] = __float2half_rn(x - __half2float(h));
    }
}

__global__ void pack_out(float* __restrict__ out, const float* __restrict__ a,
                         const float* __restrict__ b, const float* __restrict__ c) {
    const size_t n0 = (size_t)BATCH * NL0, n1 = (size_t)BATCH * NL1, n2 = (size_t)BATCH * NL2;
    size_t stride = (size_t)gridDim.x * blockDim.x;
    for (size_t i = (size_t)blockIdx.x * blockDim.x + threadIdx.x; i < n0 + n1 + n2; i += stride)
        out[i] = (i < n0) ? a[i] : (i < n0 + n1) ? b[i - n0] : c[i - n0 - n1];
}

// ---------------------------------------------------------------------------
// Fused GEMM, 128 x BN tile (fp16 split-2 operands, fp32 accumulate):
//   D = A0(hi,lo) x B0(hi,lo)^T over K0  [+ A1(hi,lo) x B1(hi,lo)^T over K1]
//   epilogue: prev? clip(0.8*prev + 0.2*(D+bias?+extra?)) : D+bias
//   writes Cf fp32 and optionally Ch/Cl fp16 split.
// TC path: SS cg1 tcgen05 kind::f16, K chunk 64 (SW128), 3 split products,
//   warp 0 owns alloc(512)+MMA+commit; 2-stage cp.async prefetch pipeline
//   (loads of chunk k+1 in flight during MMA of chunk k).
// ---------------------------------------------------------------------------
template <int BN>
__global__ void __launch_bounds__(256, 1) gemm_tc(
    const __half* __restrict__ Ah0, const __half* __restrict__ Al0,
    const __half* __restrict__ Bh0, const __half* __restrict__ Bl0, int K0,
    const __half* __restrict__ Ah1, const __half* __restrict__ Al1,
    const __half* __restrict__ Bh1, const __half* __restrict__ Bl1, int K1,
    const float* __restrict__ bias, const float* __restrict__ prev,
    const float* __restrict__ extra,
    float* __restrict__ Cf, __half* __restrict__ Ch, __half* __restrict__ Cl, int N)
{
    extern __shared__ char smem_raw[];
#if EQ_TC
    constexpr int BU = BN * 8;                    // 16B units per B half-tile
    constexpr int STAGE = 32768 + 2 * BN * 128;   // Ah,Al (16K each) + Bh,Bl
    constexpr int PT = (2048 + 2 * BU) / 256;     // 16B units / 256 threads

    const int tid = threadIdx.x, wid = tid >> 5, lid = tid & 31;
    u32 sb = (smem_u32(smem_raw) + 1023) & ~1023u;

    if (wid == 0) {
        asm volatile("tcgen05.alloc.cta_group::1.sync.aligned.shared::cta.b32 [%0], 512;"
                     :: "r"(sb) : "memory");
    }
    if (tid == 0) {
        asm volatile("mbarrier.init.shared.b64 [%0], 1;" :: "r"(sb + 16) : "memory");
        asm volatile("mbarrier.init.shared.b64 [%0], 1;" :: "r"(sb + 24) : "memory");
    }
    __syncthreads();
    u32 tmem;
    asm volatile("ld.shared.b32 %0, [%1];" : "=r"(tmem) : "r"(sb));

    const int mBase = blockIdx.y * 128, nBase = blockIdx.x * BN;
    const int nkb0 = K0 >> 6, nkb = nkb0 + (K1 >> 6);
    const u32 idesc = 0x10u | ((u32)(BN / 8) << 17) | (8u << 24);   // f32 acc, f16 A/B, M=128

    auto load_chunk = [&](int kb) {
        const int buf = kb & 1;
        const __half *Ah, *Al, *Bh, *Bl; int ldk, koff;
        if (kb < nkb0) { Ah = Ah0; Al = Al0; Bh = Bh0; Bl = Bl0; ldk = K0; koff = kb << 6; }
        else           { Ah = Ah1; Al = Al1; Bh = Bh1; Bl = Bl1; ldk = K1; koff = (kb - nkb0) << 6; }
        const u32 stg = sb + 1024 + buf * STAGE;
#pragma unroll
        for (int it = 0; it < PT; ++it) {
            int u = tid + it * 256;
            const __half* src; u32 dbase; int v;
            if (u < 1024)           { v = u;             src = Ah + (size_t)(mBase + (v >> 3)) * ldk; dbase = stg; }
            else if (u < 2048)      { v = u - 1024;      src = Al + (size_t)(mBase + (v >> 3)) * ldk; dbase = stg + 16384; }
            else if (u < 2048 + BU) { v = u - 2048;      src = Bh + (size_t)(nBase + (v >> 3)) * ldk; dbase = stg + 32768; }
            else                    { v = u - 2048 - BU; src = Bl + (size_t)(nBase + (v >> 3)) * ldk; dbase = stg + 32768 + BN * 128; }
            int row = v >> 3, slot = v & 7;
            cpa16(dbase + row * 128 + ((slot * 16) ^ ((row & 7) << 4)), src + koff + slot * 8);
        }
        asm volatile("cp.async.commit_group;" ::: "memory");
    };

    // Prologue: prefetch chunks 0 and 1.
    load_chunk(0);
    if (nkb > 1) load_chunk(1);

    for (int kb = 0; kb < nkb; ++kb) {
        const int buf = kb & 1;
        // Complete chunk kb's loads; leave chunk kb+1 (if any) in flight.
        if (kb + 1 < nkb) asm volatile("cp.async.wait_group 1;" ::: "memory");
        else              asm volatile("cp.async.wait_group 0;" ::: "memory");
        asm volatile("fence.proxy.async.shared::cta;" ::: "memory");
        __syncthreads();

        if (wid == 0 && elect_one()) {
            const u32 stg = sb + 1024 + buf * STAGE;
            u64 dAh = sdesc(stg), dAl = sdesc(stg + 16384);
            u64 dBh = sdesc(stg + 32768), dBl = sdesc(stg + 32768 + BN * 128);
#pragma unroll
            for (int ks = 0; ks < 4; ++ks) {     // 4 x K16 per chunk, 3 split products
                mma_f16_ss(tmem, dAh + ks * 2, dBh + ks * 2, idesc, (kb > 0) || (ks > 0));
                mma_f16_ss(tmem, dAh + ks * 2, dBl + ks * 2, idesc, 1);
                mma_f16_ss(tmem, dAl + ks * 2, dBh + ks * 2, idesc, 1);
            }
            asm volatile("tcgen05.commit.cta_group::1.mbarrier::arrive::one.shared::cluster.b64 [%0];"
                         :: "r"(sb + 16 + 8 * buf) : "memory");
        }
        // Refill this buffer with chunk kb+2 once MMA(kb) has consumed it.
        if (kb + 2 < nkb) {
            mbar_wait(sb + 16 + 8 * buf, (u32)((kb >> 1) & 1));
            load_chunk(kb + 2);
        }
    }
    mbar_wait(sb + 16 + 8 * ((nkb - 1) & 1), (u32)(((nkb - 1) >> 1) & 1));
    asm volatile("tcgen05.fence::after_thread_sync;" ::: "memory");

    // Epilogue: warps 0-3 left column half, 4-7 right half.
    const int row = mBase + (wid & 3) * 32 + lid;
    const int ch0 = (wid >> 2) * (BN / 2);
#pragma unroll
    for (int g = 0; g < BN / 64; ++g) {
        const int c0 = ch0 + g * 32;
        u32 r_[32];
        TC_LD32(r_, tmem + c0);
        asm volatile("tcgen05.wait::ld.sync.aligned;" ::: "memory");
        float v[32];
#pragma unroll
        for (int j = 0; j < 32; ++j) v[j] = __uint_as_float(r_[j]);
        const size_t base = (size_t)row * N + nBase + c0;
        if (bias)
#pragma unroll
            for (int j = 0; j < 32; ++j) v[j] += __ldg(bias + nBase + c0 + j);
        if (prev) {
#pragma unroll
            for (int q = 0; q < 8; ++q) {
                float4 p = *reinterpret_cast<const float4*>(prev + base + q * 4);
                float4 e = make_float4(0.f, 0.f, 0.f, 0.f);
                if (extra) e = *reinterpret_cast<const float4*>(extra + base + q * 4);
                v[4*q+0] = fminf(fmaxf(0.8f * p.x + 0.2f * (v[4*q+0] + e.x), 0.f), 1.f);
                v[4*q+1] = fminf(fmaxf(0.8f * p.y + 0.2f * (v[4*q+1] + e.y), 0.f), 1.f);
                v[4*q+2] = fminf(fmaxf(0.8f * p.z + 0.2f * (v[4*q+2] + e.z), 0.f), 1.f);
                v[4*q+3] = fminf(fmaxf(0.8f * p.w + 0.2f * (v[4*q+3] + e.w), 0.f), 1.f);
            }
        }
#pragma unroll
        for (int q = 0; q < 8; ++q)
            *reinterpret_cast<float4*>(Cf + base + q * 4) =
                make_float4(v[4*q+0], v[4*q+1], v[4*q+2], v[4*q+3]);
        if (Ch)
#pragma unroll
            for (int j = 0; j < 32; j += 2) {
                __half h0 = __float2half_rn(v[j]), h1 = __float2half_rn(v[j+1]);
                *reinterpret_cast<__half2*>(Ch + base + j) = __halves2half2(h0, h1);
                *reinterpret_cast<__half2*>(Cl + base + j) = __halves2half2(
                    __float2half_rn(v[j] - __half2float(h0)),
                    __float2half_rn(v[j+1] - __half2float(h1)));
            }
    }
    asm volatile("tcgen05.fence::before_thread_sync;" ::: "memory");
    __syncthreads();
    if (tid == 0) {
        asm volatile("mbarrier.inval.shared.b64 [%0];" :: "r"(sb + 16) : "memory");
        asm volatile("mbarrier.inval.shared.b64 [%0];" :: "r"(sb + 24) : "memory");
    }
    __syncthreads();
    if (wid == 0)
        asm volatile("tcgen05.dealloc.cta_group::1.sync.aligned.b32 %0, 512;" :: "r"(tmem));
#else
    // ---------------- SIMT fp32 fallback (non-arch-specific pass) -----------
    float* As = reinterpret_cast<float*>(smem_raw);        // [16][132]
    float* Bs = As + 16 * 132;                             // [16][132]
    const int tid = threadIdx.x;
    const int tx = tid & 15, ty = tid >> 4;
    const int mBase = blockIdx.y * 128;
    const int nkb0 = K0 >> 4, nkb = nkb0 + (K1 >> 4);
    const int lrow = tid >> 1, seg8 = tid & 1;

    for (int half = 0; half < BN / 128; ++half) {
        const int nBase = blockIdx.x * BN + half * 128;
        float acc[8][8];
#pragma unroll
        for (int i = 0; i < 8; ++i)
#pragma unroll
            for (int j = 0; j < 8; ++j) acc[i][j] = 0.f;

        for (int kb = 0; kb < nkb; ++kb) {
            const __half *Ah, *Al, *Bh, *Bl; int ldk, koff;
            if (kb < nkb0) { Ah = Ah0; Al = Al0; Bh = Bh0; Bl = Bl0; ldk = K0; koff = kb << 4; }
            else           { Ah = Ah1; Al = Al1; Bh = Bh1; Bl = Bl1; ldk = K1; koff = (kb - nkb0) << 4; }
            {
                size_t off = (size_t)(mBase + lrow) * ldk + koff + seg8 * 8;
                uint4 hv = *reinterpret_cast<const uint4*>(Ah + off);
                uint4 lv = *reinterpret_cast<const uint4*>(Al + off);
                const __half2* hh = reinterpret_cast<const __half2*>(&hv);
                const __half2* ll = reinterpret_cast<const __half2*>(&lv);
#pragma unroll
                for (int p = 0; p < 4; ++p) {
                    float2 hf = __half22float2(hh[p]);
                    float2 lf = __half22float2(ll[p]);
                    As[(seg8 * 8 + 2 * p + 0) * 132 + lrow] = hf.x + lf.x;
                    As[(seg8 * 8 + 2 * p + 1) * 132 + lrow] = hf.y + lf.y;
                }
                off = (size_t)(nBase + lrow) * ldk + koff + seg8 * 8;
                hv = *reinterpret_cast<const uint4*>(Bh + off);
                lv = *reinterpret_cast<const uint4*>(Bl + off);
#pragma unroll
                for (int p = 0; p < 4; ++p) {
                    float2 hf = __half22float2(hh[p]);
                    float2 lf = __half22float2(ll[p]);
                    Bs[(seg8 * 8 + 2 * p + 0) * 132 + lrow] = hf.x + lf.x;
                    Bs[(seg8 * 8 + 2 * p + 1) * 132 + lrow] = hf.y + lf.y;
                }
            }
            __syncthreads();
#pragma unroll
            for (int kk = 0; kk < 16; ++kk) {
                float a[8], b[8];
#pragma unroll
                for (int i = 0; i < 8; ++i) a[i] = As[kk * 132 + ty * 8 + i];
#pragma unroll
                for (int j = 0; j < 8; ++j) b[j] = Bs[kk * 132 + tx * 8 + j];
#pragma unroll
                for (int i = 0; i < 8; ++i)
#pragma unroll
                    for (int j = 0; j < 8; ++j) acc[i][j] += a[i] * b[j];
            }
            __syncthreads();
        }
#pragma unroll
        for (int i = 0; i < 8; ++i) {
            int r = mBase + ty * 8 + i;
            size_t base = (size_t)r * N + nBase + tx * 8;
            float v[8];
#pragma unroll
            for (int j = 0; j < 8; ++j) {
                v[j] = acc[i][j];
                if (bias) v[j] += bias[nBase + tx * 8 + j];
                if (prev) {
                    float e = extra ? extra[base + j] : 0.f;
                    v[j] = fminf(fmaxf(0.8f * prev[base + j] + 0.2f * (v[j] + e), 0.f), 1.f);
                }
                Cf[base + j] = v[j];
            }
            if (Ch)
#pragma unroll
                for (int j = 0; j < 8; j += 2) {
                    __half h0 = __float2half_rn(v[j]), h1 = __float2half_rn(v[j+1]);
                    *reinterpret_cast<__half2*>(Ch + base + j) = __halves2half2(h0, h1);
                    *reinterpret_cast<__half2*>(Cl + base + j) = __halves2half2(
                        __float2half_rn(v[j]   - __half2float(h0)),
                        __float2half_rn(v[j+1] - __half2float(h1)));
                }
        }
    }
#endif
}

// ---------------------------------------------------------------------------
extern "C" void kernel_launch(void* const* d_in, const int* in_sizes, int n_in,
                              void* d_out, int out_size) {
    (void)in_sizes; (void)n_in; (void)out_size;
    const float* s0   = (const float*)d_in[0];
    const float* s1   = (const float*)d_in[1];
    const float* s2   = (const float*)d_in[2];
    const float* data = (const float*)d_in[3];
    const float* W0   = (const float*)d_in[4];
    const float* b0   = (const float*)d_in[5];
    const float* W1   = (const float*)d_in[6];
    const float* b1   = (const float*)d_in[7];
    const float* W2   = (const float*)d_in[8];
    const float* b2   = (const float*)d_in[9];

    float *s0f, *s1f, *s2f, *c2;
    __half *s0h, *s0l, *s1h, *s1l, *s2h, *s2l, *dh, *dl;
    __half *W0h, *W0l, *W0Th, *W0Tl, *W1h, *W1l, *W1Th, *W1Tl, *W2h, *W2l;
    cudaGetSymbolAddress((void**)&s0f, g_s0f);   cudaGetSymbolAddress((void**)&s1f, g_s1f);
    cudaGetSymbolAddress((void**)&s2f, g_s2f);   cudaGetSymbolAddress((void**)&c2,  g_c2);
    cudaGetSymbolAddress((void**)&s0h, g_s0h);   cudaGetSymbolAddress((void**)&s0l, g_s0l);
    cudaGetSymbolAddress((void**)&s1h, g_s1h);   cudaGetSymbolAddress((void**)&s1l, g_s1l);
    cudaGetSymbolAddress((void**)&s2h, g_s2h);   cudaGetSymbolAddress((void**)&s2l, g_s2l);
    cudaGetSymbolAddress((void**)&dh,  g_dh);    cudaGetSymbolAddress((void**)&dl,  g_dl);
    cudaGetSymbolAddress((void**)&W0h, g_W0h);   cudaGetSymbolAddress((void**)&W0l, g_W0l);
    cudaGetSymbolAddress((void**)&W0Th, g_W0Th); cudaGetSymbolAddress((void**)&W0Tl, g_W0Tl);
    cudaGetSymbolAddress((void**)&W1h, g_W1h);   cudaGetSymbolAddress((void**)&W1l, g_W1l);
    cudaGetSymbolAddress((void**)&W1Th, g_W1Th); cudaGetSymbolAddress((void**)&W1Tl, g_W1Tl);
    cudaGetSymbolAddress((void**)&W2h, g_W2h);   cudaGetSymbolAddress((void**)&W2l, g_W2l);

    const size_t n0 = (size_t)BATCH * NL0, n1 = (size_t)BATCH * NL1, n2 = (size_t)BATCH * NL2;

    constexpr int SM128 = 2048 + 2 * (32768 + 2 * 128 * 128);   // 133,120 B
    constexpr int SM256 = 2048 + 2 * (32768 + 2 * 256 * 128);   // 198,656 B
    cudaFuncSetAttribute(gemm_tc<128>, cudaFuncAttributeMaxDynamicSharedMemorySize, SM128);
    cudaFuncSetAttribute(gemm_tc<256>, cudaFuncAttributeMaxDynamicSharedMemorySize, SM256);

    // prep: fp32 state copies + fp16 splits + weight splits/transposes
    cudaMemcpyAsync(s0f, s0, n0 * 4, cudaMemcpyDeviceToDevice);
    cudaMemcpyAsync(s1f, s1, n1 * 4, cudaMemcpyDeviceToDevice);
    cudaMemcpyAsync(s2f, s2, n2 * 4, cudaMemcpyDeviceToDevice);
    decompose_k<<<(int)(n0 / 4 / 256), 256>>>(s0, s0h, s0l, n0 / 4, 0);
    decompose_k<<<(int)(n1 / 4 / 256), 256>>>(s1, s1h, s1l, n1 / 4, 0);
    decompose_k<<<(int)(n2 / 4 / 256), 256>>>(s2, s2h, s2l, n2 / 4, 0);
    decompose_k<<<(int)(n2 / 4 / 256), 256>>>(data, dh, dl, n2 / 4, 1);
    decompose_k<<<(NL0 * NL1 / 4) / 256, 256>>>(W0, W0h, W0l, NL0 * NL1 / 4, 0);
    decompose_k<<<(NL1 * NL2 / 4) / 256, 256>>>(W1, W1h, W1l, NL1 * NL2 / 4, 0);
    decompose_k<<<(NL2 * NL2 / 4) / 256, 256>>>(W2, W2h, W2l, NL2 * NL2 / 4, 0);
    dim3 tb(32, 8);
    transpose_decompose_k<<<dim3(NL1 / 32, NL0 / 32), tb>>>(W0, W0Th, W0Tl, NL0, NL1);
    transpose_decompose_k<<<dim3(NL2 / 32, NL1 / 32), tb>>>(W1, W1Th, W1Tl, NL1, NL2);

    // c2 = clip(data) @ W2^T + b2  (step-invariant)
    gemm_tc<256><<<dim3(NL2 / 256, BATCH / 128), 256, SM256>>>(
        dh, dl, W2h, W2l, NL2, nullptr, nullptr, nullptr, nullptr, 0,
        b2, nullptr, nullptr, c2, nullptr, nullptr, NL2);

    for (int t = 0; t < 30; ++t) {
        const size_t cu = (size_t)(t & 1), nx = cu ^ 1;
        // n0 = clip(0.8*s0 + 0.2*(s1 @ W0^T + b0))   K=2048, N=1024
        gemm_tc<128><<<dim3(NL0 / 128, BATCH / 128), 256, SM128>>>(
            s1h + cu * n1, s1l + cu * n1, W0h, W0l, NL1,
            nullptr, nullptr, nullptr, nullptr, 0,
            b0, s0f + cu * n0, nullptr,
            s0f + nx * n0, s0h + nx * n0, s0l + nx * n0, NL0);
        // n1 = clip(0.8*s1 + 0.2*(s2 @ W1^T + s0 @ W0 + b1))   N=2048
        gemm_tc<256><<<dim3(NL1 / 256, BATCH / 128), 256, SM256>>>(
            s2h + cu * n2, s2l + cu * n2, W1h, W1l, NL2,
            s0h + cu * n0, s0l + cu * n0, W0Th, W0Tl, NL0,
            b1, s1f + cu * n1, nullptr,
            s1f + nx * n1, s1h + nx * n1, s1l + nx * n1, NL1);
        // n2 = clip(0.8*s2 + 0.2*(c2 + s1 @ W1))   N=2048
        gemm_tc<256><<<dim3(NL2 / 256, BATCH / 128), 256, SM256>>>(
            s1h + cu * n1, s1l + cu * n1, W1Th, W1Tl, NL1,
            nullptr, nullptr, nullptr, nullptr, 0,
            nullptr, s2f + cu * n2, c2,
            s2f + nx * n2, s2h + nx * n2, s2l + nx * n2, NL2);
    }

    pack_out<<<2048, 256>>>((float*)d_out, s0f, s1f, s2f);   // final in buffer 0
}

// round 13
// speedup vs baseline: 8.0973x; 1.2012x over previous
#include <cuda_runtime.h>
#include <cuda.h>
#include <cuda_fp16.h>
#include <cstdint>

typedef unsigned int u32;
typedef unsigned long long u64;

#define BATCH 2048
#define NL0 1024
#define NL1 2048
#define NL2 2048

// tcgen05/TMA are arch-specific: only emit in arch/family-specific passes.
#if defined(__CUDA_ARCH__) && (defined(__CUDA_ARCH_FEAT_SM103_ALL) || \
    defined(__CUDA_ARCH_FEAT_SM100_ALL) || \
    (defined(__CUDA_ARCH_SPECIFIC__) && (__CUDA_ARCH_SPECIFIC__ >= 1000)) || \
    (defined(__CUDA_ARCH_FAMILY_SPECIFIC__) && (__CUDA_ARCH_FAMILY_SPECIFIC__ >= 1000)))
#define EQ_TC 1
#else
#define EQ_TC 0
#endif

// ---- device scratch (no-alloc rule) ----
__device__ float  g_s0f[2][(size_t)BATCH * NL0];
__device__ float  g_s1f[2][(size_t)BATCH * NL1];
__device__ float  g_s2f[2][(size_t)BATCH * NL2];
__device__ __half g_s0h[2][(size_t)BATCH * NL0], g_s0l[2][(size_t)BATCH * NL0];
__device__ __half g_s1h[2][(size_t)BATCH * NL1], g_s1l[2][(size_t)BATCH * NL1];
__device__ __half g_s2h[2][(size_t)BATCH * NL2], g_s2l[2][(size_t)BATCH * NL2];
__device__ float  g_c2[(size_t)BATCH * NL2];
__device__ __half g_dh[(size_t)BATCH * NL2], g_dl[(size_t)BATCH * NL2];
__device__ __half g_W0h[(size_t)NL0 * NL1],  g_W0l[(size_t)NL0 * NL1];
__device__ __half g_W0Th[(size_t)NL1 * NL0], g_W0Tl[(size_t)NL1 * NL0];
__device__ __half g_W1h[(size_t)NL1 * NL2],  g_W1l[(size_t)NL1 * NL2];
__device__ __half g_W1Th[(size_t)NL2 * NL1], g_W1Tl[(size_t)NL2 * NL1];
__device__ __half g_W2h[(size_t)NL2 * NL2],  g_W2l[(size_t)NL2 * NL2];
__device__ __align__(128) CUtensorMap g_tmaps[24];

#if EQ_TC
// ---- PTX helpers ----
__device__ __forceinline__ u32 smem_u32(const void* p) {
    u32 a;
    asm("{ .reg .u64 t; cvta.to.shared.u64 t, %1; cvt.u32.u64 %0, t; }" : "=r"(a) : "l"(p));
    return a;
}
__device__ __forceinline__ bool elect_one() {
    u32 p;
    asm volatile("{\n\t.reg .pred p;\n\telect.sync _|p, 0xFFFFFFFF;\n\tselp.b32 %0, 1, 0, p;\n\t}" : "=r"(p));
    return p != 0;
}
__device__ __forceinline__ void mbar_wait(u32 mbar, u32 parity) {
    u32 done;
    asm volatile("{\n\t.reg .pred p;\n\t"
                 "mbarrier.try_wait.parity.acquire.cta.shared::cta.b64 p, [%1], %2;\n\t"
                 "selp.b32 %0, 1, 0, p;\n\t}" : "=r"(done) : "r"(mbar), "r"(parity) : "memory");
    while (!done)
        asm volatile("{\n\t.reg .pred p;\n\t"
                     "mbarrier.try_wait.parity.acquire.cta.shared::cta.b64 p, [%1], %2, 0x989680;\n\t"
                     "selp.b32 %0, 1, 0, p;\n\t}" : "=r"(done) : "r"(mbar), "r"(parity) : "memory");
}
__device__ __forceinline__ void mma_f16_ss(u32 d, u64 a, u64 b, u32 idesc, u32 acc) {
    asm volatile("{\n\t.reg .pred p;\n\tsetp.ne.u32 p, %5, 0;\n\t"
                 "tcgen05.mma.cta_group::1.kind::f16 [%0], %1, %2, %3, {%4, %4, %4, %4}, p;\n\t}"
                 :: "r"(d), "l"(a), "l"(b), "r"(idesc), "r"(0u), "r"(acc) : "memory");
}
__device__ __forceinline__ u64 sdesc(u32 addr) {   // SW128, v1, SBO=64, LBO=1
    return (2ull << 61) | (1ull << 46) | (64ull << 32) | (1ull << 16) | ((u64)(addr >> 4) & 0x3FFF);
}
__device__ __forceinline__ void tma2d(u32 dst, const void* map, int x, int y, u32 mbar) {
    asm volatile("cp.async.bulk.tensor.2d.shared::cta.global.tile.mbarrier::complete_tx::bytes "
                 "[%0], [%1, {%2, %3}], [%4];"
                 :: "r"(dst), "l"(map), "r"(x), "r"(y), "r"(mbar) : "memory");
}
#define TC_LD32(r, addr) \
    asm volatile("tcgen05.ld.sync.aligned.32x32b.x32.b32 " \
        "{%0, %1, %2, %3, %4, %5, %6, %7, %8, %9, %10, %11, %12, %13, %14, %15, " \
        " %16, %17, %18, %19, %20, %21, %22, %23, %24, %25, %26, %27, %28, %29, %30, %31}, [%32];" \
        : "=r"((r)[0]),  "=r"((r)[1]),  "=r"((r)[2]),  "=r"((r)[3]), \
          "=r"((r)[4]),  "=r"((r)[5]),  "=r"((r)[6]),  "=r"((r)[7]), \
          "=r"((r)[8]),  "=r"((r)[9]),  "=r"((r)[10]), "=r"((r)[11]), \
          "=r"((r)[12]), "=r"((r)[13]), "=r"((r)[14]), "=r"((r)[15]), \
          "=r"((r)[16]), "=r"((r)[17]), "=r"((r)[18]), "=r"((r)[19]), \
          "=r"((r)[20]), "=r"((r)[21]), "=r"((r)[22]), "=r"((r)[23]), \
          "=r"((r)[24]), "=r"((r)[25]), "=r"((r)[26]), "=r"((r)[27]), \
          "=r"((r)[28]), "=r"((r)[29]), "=r"((r)[30]), "=r"((r)[31]) \
        : "r"(addr))
#endif  // EQ_TC

// ---- prep kernels ----
__global__ void decompose_k(const float* __restrict__ in, __half* __restrict__ hi,
                            __half* __restrict__ lo, size_t n4, int clampv) {
    size_t i = (size_t)blockIdx.x * blockDim.x + threadIdx.x;
    if (i >= n4) return;
    float4 x = reinterpret_cast<const float4*>(in)[i];
    if (clampv) {
        x.x = fminf(fmaxf(x.x, 0.f), 1.f); x.y = fminf(fmaxf(x.y, 0.f), 1.f);
        x.z = fminf(fmaxf(x.z, 0.f), 1.f); x.w = fminf(fmaxf(x.w, 0.f), 1.f);
    }
    __half h0 = __float2half_rn(x.x), h1 = __float2half_rn(x.y);
    __half h2 = __float2half_rn(x.z), h3 = __float2half_rn(x.w);
    reinterpret_cast<__half2*>(hi)[2*i+0] = __halves2half2(h0, h1);
    reinterpret_cast<__half2*>(hi)[2*i+1] = __halves2half2(h2, h3);
    reinterpret_cast<__half2*>(lo)[2*i+0] = __halves2half2(
        __float2half_rn(x.x - __half2float(h0)), __float2half_rn(x.y - __half2float(h1)));
    reinterpret_cast<__half2*>(lo)[2*i+1] = __halves2half2(
        __float2half_rn(x.z - __half2float(h2)), __float2half_rn(x.w - __half2float(h3)));
}

__global__ void transpose_decompose_k(const float* __restrict__ in,
                                      __half* __restrict__ oh, __half* __restrict__ ol,
                                      int R, int C) {
    __shared__ float t[32][33];
    int c0 = blockIdx.x * 32, r0 = blockIdx.y * 32;
    int tx = threadIdx.x, ty = threadIdx.y;   // (32,8)
#pragma unroll
    for (int i = 0; i < 32; i += 8)
        t[ty + i][tx] = in[(size_t)(r0 + ty + i) * C + (c0 + tx)];
    __syncthreads();
#pragma unroll
    for (int i = 0; i < 32; i += 8) {
        float x = t[tx][ty + i];
        __half h = __float2half_rn(x);
        size_t o = (size_t)(c0 + ty + i) * R + (r0 + tx);
        oh[o] = h; ol[o] = __float2half_rn(x - __half2float(h));
    }
}

__global__ void pack_out(float* __restrict__ out, const float* __restrict__ a,
                         const float* __restrict__ b, const float* __restrict__ c) {
    const size_t n0 = (size_t)BATCH * NL0, n1 = (size_t)BATCH * NL1, n2 = (size_t)BATCH * NL2;
    size_t stride = (size_t)gridDim.x * blockDim.x;
    for (size_t i = (size_t)blockIdx.x * blockDim.x + threadIdx.x; i < n0 + n1 + n2; i += stride)
        out[i] = (i < n0) ? a[i] : (i < n0 + n1) ? b[i - n0] : c[i - n0 - n1];
}

// ---------------------------------------------------------------------------
// Fused GEMM, 128 x BN tile (fp16 split-2 operands, fp32 TMEM accumulate):
//   D = A0(hi,lo) x B0(hi,lo)^T over K0  [+ A1(hi,lo) x B1(hi,lo)^T over K1]
//   epilogue: prev? clip(0.8*prev + 0.2*(D+bias?+extra?)) : D+bias
// TC path: TMA bulk loads (4 UTMALDG per K64 chunk, SW128 boxes) into a
//   2-stage ring; full[] via expect_tx mbar, refill gated on MMA commit mbar.
//   Warp 0 runs the whole pipeline; SS cg1 tcgen05 kind::f16, 3 split products.
// Fallback: SIMT fp32 using the raw pointers.
// ---------------------------------------------------------------------------
template <int BN>
__global__ void __launch_bounds__(256, 1) gemm_tc(
    const CUtensorMap* mA0h, const CUtensorMap* mA0l,
    const CUtensorMap* mB0h, const CUtensorMap* mB0l, int K0,
    const CUtensorMap* mA1h, const CUtensorMap* mA1l,
    const CUtensorMap* mB1h, const CUtensorMap* mB1l, int K1,
    const __half* __restrict__ rAh0, const __half* __restrict__ rAl0,
    const __half* __restrict__ rBh0, const __half* __restrict__ rBl0,
    const __half* __restrict__ rAh1, const __half* __restrict__ rAl1,
    const __half* __restrict__ rBh1, const __half* __restrict__ rBl1,
    const float* __restrict__ bias, const float* __restrict__ prev,
    const float* __restrict__ extra,
    float* __restrict__ Cf, __half* __restrict__ Ch, __half* __restrict__ Cl, int N)
{
    extern __shared__ char smem_raw[];
#if EQ_TC
    constexpr int STAGE = 32768 + 2 * BN * 128;   // Ah,Al (16K each) + Bh,Bl

    const int tid = threadIdx.x, wid = tid >> 5, lid = tid & 31;
    u32 sb = (smem_u32(smem_raw) + 1023) & ~1023u;

    if (wid == 0)
        asm volatile("tcgen05.alloc.cta_group::1.sync.aligned.shared::cta.b32 [%0], 512;"
                     :: "r"(sb) : "memory");
    if (tid == 0) {
        asm volatile("mbarrier.init.shared.b64 [%0], 1;" :: "r"(sb + 16) : "memory");  // full0
        asm volatile("mbarrier.init.shared.b64 [%0], 1;" :: "r"(sb + 24) : "memory");  // full1
        asm volatile("mbarrier.init.shared.b64 [%0], 1;" :: "r"(sb + 32) : "memory");  // cmt0
        asm volatile("mbarrier.init.shared.b64 [%0], 1;" :: "r"(sb + 40) : "memory");  // cmt1
    }
    __syncthreads();
    u32 tmem;
    asm volatile("ld.shared.b32 %0, [%1];" : "=r"(tmem) : "r"(sb));

    const int mBase = blockIdx.y * 128, nBase = blockIdx.x * BN;
    const int nkb0 = K0 >> 6, nkb = nkb0 + (K1 >> 6);
    const u32 idesc = 0x10u | ((u32)(BN / 8) << 17) | (8u << 24);   // f32 acc, f16 A/B, M=128

    if (wid == 0) {
        auto load_chunk = [&](int kb) {   // single-thread: expect_tx + 4 TMA
            const int s = kb & 1;
            const CUtensorMap *Ah, *Al, *Bh, *Bl; int koff;
            if (kb < nkb0) { Ah = mA0h; Al = mA0l; Bh = mB0h; Bl = mB0l; koff = kb << 6; }
            else           { Ah = mA1h; Al = mA1l; Bh = mB1h; Bl = mB1l; koff = (kb - nkb0) << 6; }
            const u32 stg = sb + 1024 + s * STAGE;
            const u32 full = sb + 16 + 8 * s;
            asm volatile("mbarrier.arrive.expect_tx.shared.b64 _, [%0], %1;"
                         :: "r"(full), "r"((u32)STAGE) : "memory");
            tma2d(stg,                  Ah, koff, mBase, full);
            tma2d(stg + 16384,          Al, koff, mBase, full);
            tma2d(stg + 32768,          Bh, koff, nBase, full);
            tma2d(stg + 32768 + BN*128, Bl, koff, nBase, full);
        };

        if (elect_one()) {
            load_chunk(0);
            if (nkb > 1) load_chunk(1);
        }
        for (int kb = 0; kb < nkb; ++kb) {
            const int s = kb & 1;
            const u32 par = (u32)((kb >> 1) & 1);
            mbar_wait(sb + 16 + 8 * s, par);           // data ready
            if (elect_one()) {
                const u32 stg = sb + 1024 + s * STAGE;
                u64 dAh = sdesc(stg), dAl = sdesc(stg + 16384);
                u64 dBh = sdesc(stg + 32768), dBl = sdesc(stg + 32768 + BN*128);
#pragma unroll
                for (int ks = 0; ks < 4; ++ks) {       // 4 x K16, 3 split products
                    mma_f16_ss(tmem, dAh + ks * 2, dBh + ks * 2, idesc, (kb > 0) || (ks > 0));
                    mma_f16_ss(tmem, dAh + ks * 2, dBl + ks * 2, idesc, 1);
                    mma_f16_ss(tmem, dAl + ks * 2, dBh + ks * 2, idesc, 1);
                }
                asm volatile("tcgen05.commit.cta_group::1.mbarrier::arrive::one.shared::cluster.b64 [%0];"
                             :: "r"(sb + 32 + 8 * s) : "memory");
            }
            mbar_wait(sb + 32 + 8 * s, par);           // MMA(kb) done -> stage reusable
            if (kb + 2 < nkb && elect_one()) load_chunk(kb + 2);
        }
    }
    __syncthreads();
    {   // all threads confirm final MMA completion (fast path) then fence
        const int ls = (nkb - 1) & 1;
        mbar_wait(sb + 32 + 8 * ls, (u32)(((nkb - 1) >> 1) & 1));
    }
    asm volatile("tcgen05.fence::after_thread_sync;" ::: "memory");

    // Epilogue: warps 0-3 left column half, 4-7 right half.
    const int row = mBase + (wid & 3) * 32 + lid;
    const int ch0 = (wid >> 2) * (BN / 2);
#pragma unroll
    for (int g = 0; g < BN / 64; ++g) {
        const int c0 = ch0 + g * 32;
        u32 r_[32];
        TC_LD32(r_, tmem + c0);
        asm volatile("tcgen05.wait::ld.sync.aligned;" ::: "memory");
        float v[32];
#pragma unroll
        for (int j = 0; j < 32; ++j) v[j] = __uint_as_float(r_[j]);
        const size_t base = (size_t)row * N + nBase + c0;
        if (bias)
#pragma unroll
            for (int j = 0; j < 32; ++j) v[j] += __ldg(bias + nBase + c0 + j);
        if (prev) {
#pragma unroll
            for (int q = 0; q < 8; ++q) {
                float4 p = *reinterpret_cast<const float4*>(prev + base + q * 4);
                float4 e = make_float4(0.f, 0.f, 0.f, 0.f);
                if (extra) e = *reinterpret_cast<const float4*>(extra + base + q * 4);
                v[4*q+0] = fminf(fmaxf(0.8f * p.x + 0.2f * (v[4*q+0] + e.x), 0.f), 1.f);
                v[4*q+1] = fminf(fmaxf(0.8f * p.y + 0.2f * (v[4*q+1] + e.y), 0.f), 1.f);
                v[4*q+2] = fminf(fmaxf(0.8f * p.z + 0.2f * (v[4*q+2] + e.z), 0.f), 1.f);
                v[4*q+3] = fminf(fmaxf(0.8f * p.w + 0.2f * (v[4*q+3] + e.w), 0.f), 1.f);
            }
        }
#pragma unroll
        for (int q = 0; q < 8; ++q)
            *reinterpret_cast<float4*>(Cf + base + q * 4) =
                make_float4(v[4*q+0], v[4*q+1], v[4*q+2], v[4*q+3]);
        if (Ch)
#pragma unroll
            for (int j = 0; j < 32; j += 2) {
                __half h0 = __float2half_rn(v[j]), h1 = __float2half_rn(v[j+1]);
                *reinterpret_cast<__half2*>(Ch + base + j) = __halves2half2(h0, h1);
                *reinterpret_cast<__half2*>(Cl + base + j) = __halves2half2(
                    __float2half_rn(v[j] - __half2float(h0)),
                    __float2half_rn(v[j+1] - __half2float(h1)));
            }
    }
    asm volatile("tcgen05.fence::before_thread_sync;" ::: "memory");
    __syncthreads();
    if (tid == 0) {
        asm volatile("mbarrier.inval.shared.b64 [%0];" :: "r"(sb + 16) : "memory");
        asm volatile("mbarrier.inval.shared.b64 [%0];" :: "r"(sb + 24) : "memory");
        asm volatile("mbarrier.inval.shared.b64 [%0];" :: "r"(sb + 32) : "memory");
        asm volatile("mbarrier.inval.shared.b64 [%0];" :: "r"(sb + 40) : "memory");
    }
    __syncthreads();
    if (wid == 0)
        asm volatile("tcgen05.dealloc.cta_group::1.sync.aligned.b32 %0, 512;" :: "r"(tmem));
#else
    // ---------------- SIMT fp32 fallback (non-arch-specific pass) -----------
    (void)mA0h; (void)mA0l; (void)mB0h; (void)mB0l;
    (void)mA1h; (void)mA1l; (void)mB1h; (void)mB1l;
    float* As = reinterpret_cast<float*>(smem_raw);        // [16][132]
    float* Bs = As + 16 * 132;                             // [16][132]
    const int tid = threadIdx.x;
    const int tx = tid & 15, ty = tid >> 4;
    const int mBase = blockIdx.y * 128;
    const int nkb0 = K0 >> 4, nkb = nkb0 + (K1 >> 4);
    const int lrow = tid >> 1, seg8 = tid & 1;

    for (int half = 0; half < BN / 128; ++half) {
        const int nBase = blockIdx.x * BN + half * 128;
        float acc[8][8];
#pragma unroll
        for (int i = 0; i < 8; ++i)
#pragma unroll
            for (int j = 0; j < 8; ++j) acc[i][j] = 0.f;

        for (int kb = 0; kb < nkb; ++kb) {
            const __half *Ah, *Al, *Bh, *Bl; int ldk, koff;
            if (kb < nkb0) { Ah = rAh0; Al = rAl0; Bh = rBh0; Bl = rBl0; ldk = K0; koff = kb << 4; }
            else           { Ah = rAh1; Al = rAl1; Bh = rBh1; Bl = rBl1; ldk = K1; koff = (kb - nkb0) << 4; }
            {
                size_t off = (size_t)(mBase + lrow) * ldk + koff + seg8 * 8;
                uint4 hv = *reinterpret_cast<const uint4*>(Ah + off);
                uint4 lv = *reinterpret_cast<const uint4*>(Al + off);
                const __half2* hh = reinterpret_cast<const __half2*>(&hv);
                const __half2* ll = reinterpret_cast<const __half2*>(&lv);
#pragma unroll
                for (int p = 0; p < 4; ++p) {
                    float2 hf = __half22float2(hh[p]);
                    float2 lf = __half22float2(ll[p]);
                    As[(seg8 * 8 + 2 * p + 0) * 132 + lrow] = hf.x + lf.x;
                    As[(seg8 * 8 + 2 * p + 1) * 132 + lrow] = hf.y + lf.y;
                }
                off = (size_t)(nBase + lrow) * ldk + koff + seg8 * 8;
                hv = *reinterpret_cast<const uint4*>(Bh + off);
                lv = *reinterpret_cast<const uint4*>(Bl + off);
#pragma unroll
                for (int p = 0; p < 4; ++p) {
                    float2 hf = __half22float2(hh[p]);
                    float2 lf = __half22float2(ll[p]);
                    Bs[(seg8 * 8 + 2 * p + 0) * 132 + lrow] = hf.x + lf.x;
                    Bs[(seg8 * 8 + 2 * p + 1) * 132 + lrow] = hf.y + lf.y;
                }
            }
            __syncthreads();
#pragma unroll
            for (int kk = 0; kk < 16; ++kk) {
                float a[8], b[8];
#pragma unroll
                for (int i = 0; i < 8; ++i) a[i] = As[kk * 132 + ty * 8 + i];
#pragma unroll
                for (int j = 0; j < 8; ++j) b[j] = Bs[kk * 132 + tx * 8 + j];
#pragma unroll
                for (int i = 0; i < 8; ++i)
#pragma unroll
                    for (int j = 0; j < 8; ++j) acc[i][j] += a[i] * b[j];
            }
            __syncthreads();
        }
#pragma unroll
        for (int i = 0; i < 8; ++i) {
            int r = mBase + ty * 8 + i;
            size_t base = (size_t)r * N + nBase + tx * 8;
            float v[8];
#pragma unroll
            for (int j = 0; j < 8; ++j) {
                v[j] = acc[i][j];
                if (bias) v[j] += bias[nBase + tx * 8 + j];
                if (prev) {
                    float e = extra ? extra[base + j] : 0.f;
                    v[j] = fminf(fmaxf(0.8f * prev[base + j] + 0.2f * (v[j] + e), 0.f), 1.f);
                }
                Cf[base + j] = v[j];
            }
            if (Ch)
#pragma unroll
                for (int j = 0; j < 8; j += 2) {
                    __half h0 = __float2half_rn(v[j]), h1 = __float2half_rn(v[j+1]);
                    *reinterpret_cast<__half2*>(Ch + base + j) = __halves2half2(h0, h1);
                    *reinterpret_cast<__half2*>(Cl + base + j) = __halves2half2(
                        __float2half_rn(v[j]   - __half2float(h0)),
                        __float2half_rn(v[j+1] - __half2float(h1)));
                }
        }
    }
#endif
}

// ---------------------------------------------------------------------------
typedef CUresult (*PFN_tmapenc)(CUtensorMap*, CUtensorMapDataType, cuuint32_t, void*,
                                const cuuint64_t*, const cuuint64_t*, const cuuint32_t*,
                                const cuuint32_t*, CUtensorMapInterleave, CUtensorMapSwizzle,
                                CUtensorMapL2promotion, CUtensorMapFloatOOBfill);

static void enc_map(PFN_tmapenc enc, CUtensorMap* m, const void* base,
                    uint64_t K, uint64_t R, uint32_t boxR) {
    cuuint64_t dims[2]    = {K, R};
    cuuint64_t strides[1] = {K * 2};
    cuuint32_t box[2]     = {64, boxR};           // 64 fp16 = 128B = SW128 span
    cuuint32_t es[2]      = {1, 1};
    enc(m, CU_TENSOR_MAP_DATA_TYPE_FLOAT16, 2, const_cast<void*>(base),
        dims, strides, box, es, CU_TENSOR_MAP_INTERLEAVE_NONE,
        CU_TENSOR_MAP_SWIZZLE_128B, CU_TENSOR_MAP_L2_PROMOTION_L2_128B,
        CU_TENSOR_MAP_FLOAT_OOB_FILL_NONE);
}

extern "C" void kernel_launch(void* const* d_in, const int* in_sizes, int n_in,
                              void* d_out, int out_size) {
    (void)in_sizes; (void)n_in; (void)out_size;
    const float* s0   = (const float*)d_in[0];
    const float* s1   = (const float*)d_in[1];
    const float* s2   = (const float*)d_in[2];
    const float* data = (const float*)d_in[3];
    const float* W0   = (const float*)d_in[4];
    const float* b0   = (const float*)d_in[5];
    const float* W1   = (const float*)d_in[6];
    const float* b1   = (const float*)d_in[7];
    const float* W2   = (const float*)d_in[8];
    const float* b2   = (const float*)d_in[9];

    float *s0f, *s1f, *s2f, *c2;
    __half *s0h, *s0l, *s1h, *s1l, *s2h, *s2l, *dh, *dl;
    __half *W0h, *W0l, *W0Th, *W0Tl, *W1h, *W1l, *W1Th, *W1Tl, *W2h, *W2l;
    cudaGetSymbolAddress((void**)&s0f, g_s0f);   cudaGetSymbolAddress((void**)&s1f, g_s1f);
    cudaGetSymbolAddress((void**)&s2f, g_s2f);   cudaGetSymbolAddress((void**)&c2,  g_c2);
    cudaGetSymbolAddress((void**)&s0h, g_s0h);   cudaGetSymbolAddress((void**)&s0l, g_s0l);
    cudaGetSymbolAddress((void**)&s1h, g_s1h);   cudaGetSymbolAddress((void**)&s1l, g_s1l);
    cudaGetSymbolAddress((void**)&s2h, g_s2h);   cudaGetSymbolAddress((void**)&s2l, g_s2l);
    cudaGetSymbolAddress((void**)&dh,  g_dh);    cudaGetSymbolAddress((void**)&dl,  g_dl);
    cudaGetSymbolAddress((void**)&W0h, g_W0h);   cudaGetSymbolAddress((void**)&W0l, g_W0l);
    cudaGetSymbolAddress((void**)&W0Th, g_W0Th); cudaGetSymbolAddress((void**)&W0Tl, g_W0Tl);
    cudaGetSymbolAddress((void**)&W1h, g_W1h);   cudaGetSymbolAddress((void**)&W1l, g_W1l);
    cudaGetSymbolAddress((void**)&W1Th, g_W1Th); cudaGetSymbolAddress((void**)&W1Tl, g_W1Tl);
    cudaGetSymbolAddress((void**)&W2h, g_W2h);   cudaGetSymbolAddress((void**)&W2l, g_W2l);

    const size_t n0 = (size_t)BATCH * NL0, n1 = (size_t)BATCH * NL1, n2 = (size_t)BATCH * NL2;

    // ---- tensormaps (host-built, graph-captured H2D into device array) ----
    PFN_tmapenc enc = nullptr;
    cudaDriverEntryPointQueryResult qr;
    cudaGetDriverEntryPointByVersion("cuTensorMapEncodeTiled", (void**)&enc, 12000,
                                     cudaEnableDefault, &qr);
    static CUtensorMap h_maps[24];
    // A-role maps (box rows = 128)
    enc_map(enc, &h_maps[0],  s0h,      NL0, BATCH, 128);
    enc_map(enc, &h_maps[1],  s0h + n0, NL0, BATCH, 128);
    enc_map(enc, &h_maps[2],  s0l,      NL0, BATCH, 128);
    enc_map(enc, &h_maps[3],  s0l + n0, NL0, BATCH, 128);
    enc_map(enc, &h_maps[4],  s1h,      NL1, BATCH, 128);
    enc_map(enc, &h_maps[5],  s1h + n1, NL1, BATCH, 128);
    enc_map(enc, &h_maps[6],  s1l,      NL1, BATCH, 128);
    enc_map(enc, &h_maps[7],  s1l + n1, NL1, BATCH, 128);
    enc_map(enc, &h_maps[8],  s2h,      NL2, BATCH, 128);
    enc_map(enc, &h_maps[9],  s2h + n2, NL2, BATCH, 128);
    enc_map(enc, &h_maps[10], s2l,      NL2, BATCH, 128);
    enc_map(enc, &h_maps[11], s2l + n2, NL2, BATCH, 128);
    enc_map(enc, &h_maps[12], dh,       NL2, BATCH, 128);
    enc_map(enc, &h_maps[13], dl,       NL2, BATCH, 128);
    // B-role maps
    enc_map(enc, &h_maps[14], W0h,  NL1, NL0, 128);   // G1, BN=128
    enc_map(enc, &h_maps[15], W0l,  NL1, NL0, 128);
    enc_map(enc, &h_maps[16], W0Th, NL0, NL1, 256);   // G2 seg2
    enc_map(enc, &h_maps[17], W0Tl, NL0, NL1, 256);
    enc_map(enc, &h_maps[18], W1h,  NL2, NL1, 256);   // G2 seg1
    enc_map(enc, &h_maps[19], W1l,  NL2, NL1, 256);
    enc_map(enc, &h_maps[20], W1Th, NL1, NL2, 256);   // G3
    enc_map(enc, &h_maps[21], W1Tl, NL1, NL2, 256);
    enc_map(enc, &h_maps[22], W2h,  NL2, NL2, 256);   // c2
    enc_map(enc, &h_maps[23], W2l,  NL2, NL2, 256);
    void* d_tm;
    cudaGetSymbolAddress(&d_tm, g_tmaps);
    cudaMemcpyAsync(d_tm, h_maps, sizeof(h_maps), cudaMemcpyHostToDevice);
    const CUtensorMap* M = (const CUtensorMap*)d_tm;

    constexpr int SM128 = 2048 + 2 * (32768 + 2 * 128 * 128);   // 133,120 B
    constexpr int SM256 = 2048 + 2 * (32768 + 2 * 256 * 128);   // 198,656 B
    cudaFuncSetAttribute(gemm_tc<128>, cudaFuncAttributeMaxDynamicSharedMemorySize, SM128);
    cudaFuncSetAttribute(gemm_tc<256>, cudaFuncAttributeMaxDynamicSharedMemorySize, SM256);

    // prep: fp32 state copies + fp16 splits + weight splits/transposes
    cudaMemcpyAsync(s0f, s0, n0 * 4, cudaMemcpyDeviceToDevice);
    cudaMemcpyAsync(s1f, s1, n1 * 4, cudaMemcpyDeviceToDevice);
    cudaMemcpyAsync(s2f, s2, n2 * 4, cudaMemcpyDeviceToDevice);
    decompose_k<<<(int)(n0 / 4 / 256), 256>>>(s0, s0h, s0l, n0 / 4, 0);
    decompose_k<<<(int)(n1 / 4 / 256), 256>>>(s1, s1h, s1l, n1 / 4, 0);
    decompose_k<<<(int)(n2 / 4 / 256), 256>>>(s2, s2h, s2l, n2 / 4, 0);
    decompose_k<<<(int)(n2 / 4 / 256), 256>>>(data, dh, dl, n2 / 4, 1);
    decompose_k<<<(NL0 * NL1 / 4) / 256, 256>>>(W0, W0h, W0l, NL0 * NL1 / 4, 0);
    decompose_k<<<(NL1 * NL2 / 4) / 256, 256>>>(W1, W1h, W1l, NL1 * NL2 / 4, 0);
    decompose_k<<<(NL2 * NL2 / 4) / 256, 256>>>(W2, W2h, W2l, NL2 * NL2 / 4, 0);
    dim3 tb(32, 8);
    transpose_decompose_k<<<dim3(NL1 / 32, NL0 / 32), tb>>>(W0, W0Th, W0Tl, NL0, NL1);
    transpose_decompose_k<<<dim3(NL2 / 32, NL1 / 32), tb>>>(W1, W1Th, W1Tl, NL1, NL2);

    // c2 = clip(data) @ W2^T + b2  (step-invariant)
    gemm_tc<256><<<dim3(NL2 / 256, BATCH / 128), 256, SM256>>>(
        M+12, M+13, M+22, M+23, NL2, nullptr, nullptr, nullptr, nullptr, 0,
        dh, dl, W2h, W2l, nullptr, nullptr, nullptr, nullptr,
        b2, nullptr, nullptr, c2, nullptr, nullptr, NL2);

    for (int t = 0; t < 30; ++t) {
        const int cu = t & 1, nx = cu ^ 1;
        const size_t cuz = (size_t)cu, nxz = (size_t)nx;
        // n0 = clip(0.8*s0 + 0.2*(s1 @ W0^T + b0))   K=2048, N=1024
        gemm_tc<128><<<dim3(NL0 / 128, BATCH / 128), 256, SM128>>>(
            M+4+cu, M+6+cu, M+14, M+15, NL1, nullptr, nullptr, nullptr, nullptr, 0,
            s1h + cuz * n1, s1l + cuz * n1, W0h, W0l, nullptr, nullptr, nullptr, nullptr,
            b0, s0f + cuz * n0, nullptr,
            s0f + nxz * n0, s0h + nxz * n0, s0l + nxz * n0, NL0);
        // n1 = clip(0.8*s1 + 0.2*(s2 @ W1^T + s0 @ W0 + b1))   N=2048
        gemm_tc<256><<<dim3(NL1 / 256, BATCH / 128), 256, SM256>>>(
            M+8+cu, M+10+cu, M+18, M+19, NL2, M+0+cu, M+2+cu, M+16, M+17, NL0,
            s2h + cuz * n2, s2l + cuz * n2, W1h, W1l,
            s0h + cuz * n0, s0l + cuz * n0, W0Th, W0Tl,
            b1, s1f + cuz * n1, nullptr,
            s1f + nxz * n1, s1h + nxz * n1, s1l + nxz * n1, NL1);
        // n2 = clip(0.8*s2 + 0.2*(c2 + s1 @ W1))   N=2048
        gemm_tc<256><<<dim3(NL2 / 256, BATCH / 128), 256, SM256>>>(
            M+4+cu, M+6+cu, M+20, M+21, NL1, nullptr, nullptr, nullptr, nullptr, 0,
            s1h + cuz * n1, s1l + cuz * n1, W1Th, W1Tl, nullptr, nullptr, nullptr, nullptr,
            nullptr, s2f + cuz * n2, c2,
            s2f + nxz * n2, s2h + nxz * n2, s2l + nxz * n2, NL2);
    }

    pack_out<<<2048, 256>>>((float*)d_out, s0f, s1f, s2f);   // final in buffer 0
}